// round 1
// baseline (speedup 1.0000x reference)
#include <cuda_runtime.h>
#include <math.h>

#define NBATCH 16
#define QN 900
#define HID 256
#define NBINS 36
#define NB2 1296
#define BIGV 1e9f

#define TILE 64
#define NTI 15      // ceil(900/64)
#define NTP 120     // NTI*(NTI+1)/2

// ---------------- device globals (no allocations allowed) ----------------
__device__ float g_nq[NBATCH * QN * HID];           // normalized fused features
__device__ float g_ang[NBATCH * QN];
__device__ int   g_bin[NBATCH * QN];
__device__ unsigned long long g_seg[NBATCH * NB2];  // (ordfloat<<32)|(~pairidx)
__device__ unsigned int g_top4[NBATCH * 4];         // top-4 encoded pair sims
__device__ float g_res[NBATCH * 4];                 // coop, comp, validflag

// ---------------- ordered-float encoding ----------------
__device__ __forceinline__ unsigned encf(float f) {
    unsigned u = __float_as_uint(f);
    return (u & 0x80000000u) ? ~u : (u | 0x80000000u);
}
__device__ __forceinline__ float decf(unsigned u) {
    unsigned v = (u & 0x80000000u) ? (u ^ 0x80000000u) : ~u;
    return __uint_as_float(v);
}

// ---------------- init ----------------
__global__ void k_init() {
    int t = blockIdx.x * blockDim.x + threadIdx.x;
    if (t < NBATCH * NB2) g_seg[t] = 0ULL;
    if (t < NBATCH * 4)   g_top4[t] = 0u;
}

// ---------------- prep: angles, bins, fused + normalize ----------------
__global__ __launch_bounds__(HID) void k_prep(const float* __restrict__ qf,
                                              const float* __restrict__ pa,
                                              const float* __restrict__ W) {
    int bq = blockIdx.x;            // b*QN + q
    int t  = threadIdx.x;

    float x = pa[bq * 2 + 0], y = pa[bq * 2 + 1];
    // double atan2 rounded to f32 (best match to reference f32 arctan2)
    float a = (float)atan2((double)y, (double)x);
    const float TWO_PI_F = 6.283185307179586f;
    if (a < 0.0f) a += TWO_PI_F;    // jnp.mod for |a|<2pi
    const float BIN_SIZE_F = (float)(6.283185307179586476925287 / 36.0);
    int bin = (int)(a / BIN_SIZE_F);
    bin = min(max(bin, 0), NBINS - 1);

    float f = qf[bq * HID + t] + W[bin * HID + t];
    float ss = f * f;
    #pragma unroll
    for (int o = 16; o; o >>= 1) ss += __shfl_xor_sync(0xffffffffu, ss, o);
    __shared__ float wsum[8];
    if ((t & 31) == 0) wsum[t >> 5] = ss;
    __syncthreads();
    float tot = 0.0f;
    #pragma unroll
    for (int w = 0; w < 8; w++) tot += wsum[w];
    float nrm = fmaxf(sqrtf(tot), 1e-12f);
    g_nq[bq * HID + t] = f / nrm;
    if (t == 0) { g_ang[bq] = a; g_bin[bq] = bin; }
}

// ---------------- pair kernel: triangular tiled GEMM + segment argmax ----------------
__global__ __launch_bounds__(256) void k_pair() {
    __shared__ __align__(16) float As[TILE][TILE + 4];
    __shared__ __align__(16) float Bs[TILE][TILE + 4];
    __shared__ unsigned long long sseg[NB2];
    __shared__ int sbi[TILE], sbj[TILE];
    __shared__ unsigned stop4[4];

    int b = blockIdx.y;
    int p = blockIdx.x;
    int ti = 0, rem = p;
    while (rem >= NTI - ti) { rem -= NTI - ti; ti++; }
    int tj = ti + rem;
    int i0 = ti * TILE, j0 = tj * TILE;

    const float* nq = g_nq + (size_t)b * QN * HID;
    int tid = threadIdx.x;

    for (int s = tid; s < NB2; s += 256) sseg[s] = 0ULL;
    if (tid < 4) stop4[tid] = 0u;
    if (tid < TILE) {
        int gi = i0 + tid; sbi[tid] = (gi < QN) ? g_bin[b * QN + gi] : 0;
        int gj = j0 + tid; sbj[tid] = (gj < QN) ? g_bin[b * QN + gj] : 0;
    }

    float acc[4][4];
    #pragma unroll
    for (int r = 0; r < 4; r++)
        #pragma unroll
        for (int c = 0; c < 4; c++) acc[r][c] = 0.0f;

    int mr = tid & 15, mc = tid >> 4;

    for (int kb = 0; kb < HID; kb += TILE) {
        __syncthreads();
        #pragma unroll
        for (int l = 0; l < 16; l++) {
            int idx = tid + 256 * l;       // 0..4095
            int row = idx >> 6, kk = idx & 63;
            int gi = i0 + row;
            As[kk][row] = (gi < QN) ? nq[gi * HID + kb + kk] : 0.0f;
            int gj = j0 + row;
            Bs[kk][row] = (gj < QN) ? nq[gj * HID + kb + kk] : 0.0f;
        }
        __syncthreads();
        #pragma unroll 8
        for (int k = 0; k < TILE; k++) {
            float4 a4 = *(const float4*)&As[k][mr * 4];
            float4 b4 = *(const float4*)&Bs[k][mc * 4];
            float av[4] = {a4.x, a4.y, a4.z, a4.w};
            float bv[4] = {b4.x, b4.y, b4.z, b4.w};
            #pragma unroll
            for (int r = 0; r < 4; r++)
                #pragma unroll
                for (int c = 0; c < 4; c++)
                    acc[r][c] = fmaf(av[r], bv[c], acc[r][c]);
        }
    }
    __syncthreads();

    // epilogue: segment argmax + local top4
    unsigned lt[4] = {0u, 0u, 0u, 0u};
    #pragma unroll
    for (int r = 0; r < 4; r++) {
        int gi = i0 + mr * 4 + r;
        #pragma unroll
        for (int c = 0; c < 4; c++) {
            int gj = j0 + mc * 4 + c;
            if (gi < QN && gj < QN && gi < gj) {
                float v = acc[r][c];
                unsigned ev = encf(v);
                if (ev > lt[3]) {
                    if (ev > lt[0])      { lt[3]=lt[2]; lt[2]=lt[1]; lt[1]=lt[0]; lt[0]=ev; }
                    else if (ev > lt[1]) { lt[3]=lt[2]; lt[2]=lt[1]; lt[1]=ev; }
                    else if (ev > lt[2]) { lt[3]=lt[2]; lt[2]=ev; }
                    else                 { lt[3]=ev; }
                }
                int bi = sbi[mr * 4 + r], bj = sbj[mc * 4 + c];
                int sgm = min(bi, bj) * NBINS + max(bi, bj);
                unsigned long long key =
                    ((unsigned long long)ev << 32) |
                    (unsigned long long)(0xFFFFFFFFu - (unsigned)(gi * QN + gj));
                atomicMax(&sseg[sgm], key);
            }
        }
    }
    // merge local top4 into shared top4 (bubble cascade; exact multiset)
    #pragma unroll
    for (int q4 = 0; q4 < 4; q4++) {
        unsigned v = lt[q4];
        if (!v) break;
        #pragma unroll
        for (int sl = 0; sl < 4; sl++) {
            unsigned old = atomicMax(&stop4[sl], v);
            v = min(v, old);
            if (!v) break;
        }
    }
    __syncthreads();

    unsigned long long* gs = g_seg + (size_t)b * NB2;
    for (int s = tid; s < NB2; s += 256) {
        unsigned long long k = sseg[s];
        if (k) atomicMax(&gs[s], k);
    }
    if (tid == 0) {
        unsigned* gt = g_top4 + b * 4;
        #pragma unroll
        for (int q4 = 0; q4 < 4; q4++) {
            unsigned v = stop4[q4];
            if (!v) continue;
            for (int sl = 0; sl < 4; sl++) {
                unsigned old = atomicMax(&gt[sl], v);
                v = min(v, old);
                if (!v) break;
            }
        }
    }
}

// ---------------- finalize helpers ----------------
__device__ __forceinline__ int blockReduceInt(int v, int* sh, int tid) {
    sh[tid] = v; __syncthreads();
    #pragma unroll
    for (int o = 128; o; o >>= 1) { if (tid < o) sh[tid] += sh[tid + o]; __syncthreads(); }
    int r = sh[0]; __syncthreads();
    return r;
}
__device__ __forceinline__ float blockReduceFloat(float v, float* sh, int tid) {
    sh[tid] = v; __syncthreads();
    #pragma unroll
    for (int o = 128; o; o >>= 1) { if (tid < o) sh[tid] += sh[tid + o]; __syncthreads(); }
    float r = sh[0]; __syncthreads();
    return r;
}
__device__ void bitonic2048(float* a, int tid) {
    for (int k = 2; k <= 2048; k <<= 1) {
        for (int j = k >> 1; j > 0; j >>= 1) {
            for (int i = tid; i < 2048; i += 256) {
                int ixj = i ^ j;
                if (ixj > i) {
                    bool up = ((i & k) == 0);
                    float x = a[i], y = a[ixj];
                    if (up ? (x > y) : (x < y)) { a[i] = y; a[ixj] = x; }
                }
            }
            __syncthreads();
        }
    }
}
// masked quantile, q = 1 - 1/(n+1), linear interp on sorted array (length NB2 logical)
__device__ __forceinline__ float quantv(const float* s, int n) {
    float nf = (float)n;
    float q  = 1.0f - 1.0f / (nf + 1.0f);
    float pos = q * fmaxf(nf - 1.0f, 0.0f);
    int lo = (int)floorf(pos); lo = min(max(lo, 0), NB2 - 1);
    int hi = (int)ceilf(pos);  hi = min(max(hi, 0), NB2 - 1);
    float frac = pos - (float)lo;
    return s[lo] + (s[hi] - s[lo]) * frac;
}

// ---------------- finalize: one block per batch ----------------
__global__ __launch_bounds__(256) void k_final() {
    __shared__ float ssel[NB2], sdd[NB2], sai[NB2], saj[NB2];
    __shared__ unsigned char svld[NB2], smF[NB2];
    __shared__ float ssort[2048];
    __shared__ float redf[256];
    __shared__ int   redi[256];

    const int tid = threadIdx.x;
    const int b   = blockIdx.x;
    const float* ang = g_ang + b * QN;
    const float TWO_PI_F  = 6.283185307179586f;
    const float HALF_PI_F = 1.5707963267948966f;

    for (int s = tid; s < NB2; s += 256) {
        unsigned long long key = g_seg[(size_t)b * NB2 + s];
        float v = 0.f, ai = 0.f, aj = 0.f, d = 0.f;
        unsigned char vl = 0;
        if (key) {
            vl = 1;
            v = decf((unsigned)(key >> 32));
            unsigned ij = 0xFFFFFFFFu - (unsigned)key;
            int i = ij / QN, j = ij - i * QN;
            ai = ang[i]; aj = ang[j];
            float diff = fabsf(ai - aj);
            d = fminf(fminf(diff, TWO_PI_F - diff), HALF_PI_F);
        }
        ssel[s] = v; sai[s] = ai; saj[s] = aj; sdd[s] = d; svld[s] = vl;
    }
    __syncthreads();

    // S = number of valid segments
    int c = 0;
    for (int s = tid; s < NB2; s += 256) c += svld[s];
    int S = blockReduceInt(c, redi, tid);

    // quantile threshold over valid sel sims
    for (int i = tid; i < 2048; i += 256)
        ssort[i] = (i < NB2 && svld[i]) ? ssel[i] : BIGV;
    __syncthreads();
    bitonic2048(ssort, tid);
    float thr = quantv(ssort, S);
    __syncthreads();

    // mask1
    c = 0;
    for (int s = tid; s < NB2; s += 256) {
        unsigned char m = (svld[s] && ssel[s] > thr) ? 1 : 0;
        smF[s] = m; c += m;
    }
    int c1 = blockReduceInt(c, redi, tid);

    // fallback: th2 = 4th-largest pair sim (== 8th of symmetric-duplicated matrix)
    float th2 = decf(g_top4[b * 4 + 3]);
    bool use_fb = (c1 < 2);
    c = 0;
    for (int s = tid; s < NB2; s += 256) {
        unsigned char m = use_fb ? ((svld[s] && ssel[s] >= th2) ? 1 : 0) : smF[s];
        smF[s] = m; c += m;
    }
    int cnt = blockReduceInt(c, redi, tid);

    // median of circular distances over maskF (lower-middle order statistic)
    for (int i = tid; i < 2048; i += 256)
        ssort[i] = (i < NB2 && smF[i]) ? sdd[i] : BIGV;
    __syncthreads();
    bitonic2048(ssort, tid);
    int medi = (cnt > 0) ? ((cnt - 1) >> 1) : 0;
    float med = ssort[medi];
    float alpha = fminf(fmaxf(med, (float)(3.14159265358979323846 / 36.0)), HALF_PI_F);
    __syncthreads();

    // cooperative loss
    float fs = 0.f; int nc = 0;
    for (int s = tid; s < NB2; s += 256) {
        if (smF[s] && sdd[s] <= alpha) {
            float ai = sai[s], aj = saj[s];
            float mean = atan2f((sinf(ai) + sinf(aj)) * 0.5f,
                                (cosf(ai) + cosf(aj)) * 0.5f);
            float d1 = fabsf(ai - mean); d1 = fminf(fminf(d1, TWO_PI_F - d1), HALF_PI_F);
            float d2 = fabsf(aj - mean); d2 = fminf(fminf(d2, TWO_PI_F - d2), HALF_PI_F);
            fs += d1 * d1 + d2 * d2;
            nc++;
        }
    }
    float coop_sum = blockReduceFloat(fs, redf, tid);
    int n_coop = blockReduceInt(nc, redi, tid);
    float coop_b = coop_sum / (float)max(n_coop, 1);

    // competitive loss
    c = 0;
    for (int s = tid; s < NB2; s += 256)
        if (smF[s] && sdd[s] > alpha) c++;
    int n_comp = blockReduceInt(c, redi, tid);
    for (int i = tid; i < 2048; i += 256)
        ssort[i] = (i < NB2 && smF[i] && sdd[i] > alpha) ? ssel[i] : BIGV;
    __syncthreads();
    bitonic2048(ssort, tid);
    float margin = quantv(ssort, n_comp);
    __syncthreads();
    fs = 0.f;
    for (int s = tid; s < NB2; s += 256) {
        if (smF[s] && sdd[s] > alpha) {
            float viol = fmaxf(ssel[s] - margin, 0.f);
            fs += viol * viol;
        }
    }
    float comp_sum = blockReduceFloat(fs, redf, tid);
    float comp_b = comp_sum / (float)max(n_comp, 1);

    if (tid == 0) {
        g_res[b * 4 + 0] = coop_b;
        g_res[b * 4 + 1] = comp_b;
        g_res[b * 4 + 2] = (cnt > 0) ? 1.0f : 0.0f;
    }
}

// ---------------- combine ----------------
__global__ void k_out(float* out) {
    if (threadIdx.x == 0 && blockIdx.x == 0) {
        float cs = 0.f, ps = 0.f; int nv = 0;
        for (int b = 0; b < NBATCH; b++) {
            cs += g_res[b * 4 + 0];
            ps += g_res[b * 4 + 1];
            nv += (g_res[b * 4 + 2] > 0.f) ? 1 : 0;
        }
        float denom = (float)max(nv, 1);
        out[0] = cs / denom;
        out[1] = ps / denom;
    }
}

// ---------------- launch ----------------
extern "C" void kernel_launch(void* const* d_in, const int* in_sizes, int n_in,
                              void* d_out, int out_size) {
    const float* qf = (const float*)d_in[0];   // [16,900,256]
    const float* pa = (const float*)d_in[1];   // [16,900,2]
    const float* W  = (const float*)d_in[2];   // [36,256]
    float* out = (float*)d_out;

    k_init<<<(NBATCH * NB2 + 255) / 256, 256>>>();
    k_prep<<<NBATCH * QN, HID>>>(qf, pa, W);
    dim3 g2(NTP, NBATCH);
    k_pair<<<g2, 256>>>();
    k_final<<<NBATCH, 256>>>();
    k_out<<<1, 32>>>(out);
}

// round 2
// speedup vs baseline: 2.8483x; 2.8483x over previous
#include <cuda_runtime.h>
#include <math.h>

#define NBATCH 16
#define QN 900
#define HID 256
#define NBINS 36
#define NB2 1296
#define BIGV 1e9f

#define BM 128
#define BK 16
#define NTI2 8      // ceil(900/128)
#define NTP2 36     // 8*9/2

// ---------------- device globals ----------------
__device__ float g_nq[NBATCH * QN * HID];
__device__ float g_ang[NBATCH * QN];
__device__ int   g_bin[NBATCH * QN];
__device__ unsigned long long g_seg[NBATCH * NB2];  // (ordfloat<<32)|(~pairidx)
__device__ unsigned int g_top4[NBATCH * 4];
__device__ float g_res[NBATCH * 4];

// ---------------- ordered-float encoding ----------------
__device__ __forceinline__ unsigned encf(float f) {
    unsigned u = __float_as_uint(f);
    return (u & 0x80000000u) ? ~u : (u | 0x80000000u);
}
__device__ __forceinline__ float decf(unsigned u) {
    unsigned v = (u & 0x80000000u) ? (u ^ 0x80000000u) : ~u;
    return __uint_as_float(v);
}

// packed f32x2 fma (sm_103a FFMA2 — ptxas never auto-emits this)
__device__ __forceinline__ void ffma2(unsigned long long& d,
                                      unsigned long long a, unsigned long long b) {
    asm("fma.rn.f32x2 %0, %1, %2, %0;" : "+l"(d) : "l"(a), "l"(b));
}
__device__ __forceinline__ unsigned long long pack2(float v) {
    unsigned long long r;
    asm("mov.b64 %0, {%1, %1};" : "=l"(r) : "f"(v));
    return r;
}
__device__ __forceinline__ void unpack2(unsigned long long p, float& lo, float& hi) {
    asm("mov.b64 {%0, %1}, %2;" : "=f"(lo), "=f"(hi) : "l"(p));
}

// ---------------- init ----------------
__global__ void k_init() {
    int t = blockIdx.x * blockDim.x + threadIdx.x;
    if (t < NBATCH * NB2) g_seg[t] = 0ULL;
    if (t < NBATCH * 4)   g_top4[t] = 0u;
}

// ---------------- prep ----------------
__global__ __launch_bounds__(HID) void k_prep(const float* __restrict__ qf,
                                              const float* __restrict__ pa,
                                              const float* __restrict__ W) {
    __shared__ int sh_bin;
    __shared__ float wsum[8];
    int bq = blockIdx.x;
    int t  = threadIdx.x;

    if (t == 0) {
        float x = pa[bq * 2 + 0], y = pa[bq * 2 + 1];
        float a = (float)atan2((double)y, (double)x);
        const float TWO_PI_F = 6.283185307179586f;
        if (a < 0.0f) a += TWO_PI_F;
        const float BIN_SIZE_F = (float)(6.283185307179586476925287 / 36.0);
        int bin = (int)(a / BIN_SIZE_F);
        bin = min(max(bin, 0), NBINS - 1);
        sh_bin = bin;
        g_ang[bq] = a; g_bin[bq] = bin;
    }
    __syncthreads();
    int bin = sh_bin;

    float f = qf[bq * HID + t] + W[bin * HID + t];
    float ss = f * f;
    #pragma unroll
    for (int o = 16; o; o >>= 1) ss += __shfl_xor_sync(0xffffffffu, ss, o);
    if ((t & 31) == 0) wsum[t >> 5] = ss;
    __syncthreads();
    float tot = 0.0f;
    #pragma unroll
    for (int w = 0; w < 8; w++) tot += wsum[w];
    float nrm = fmaxf(sqrtf(tot), 1e-12f);
    g_nq[bq * HID + t] = f / nrm;
}

// ---------------- pair kernel: 128x128 FFMA2 GEMM + segment argmax ----------------
__global__ __launch_bounds__(256, 2) void k_pair() {
    __shared__ __align__(16) float As[2][BK][BM + 4];
    __shared__ __align__(16) float Bs[2][BK][BM + 4];
    __shared__ unsigned long long sseg[NB2];
    __shared__ int sbi[BM], sbj[BM];
    __shared__ unsigned stop4[4];

    const int b = blockIdx.y;
    int p = blockIdx.x;
    int ti = 0, rem = p;
    while (rem >= NTI2 - ti) { rem -= NTI2 - ti; ti++; }
    const int tj = ti + rem;
    const int i0 = ti * BM, j0 = tj * BM;

    const float* __restrict__ nq = g_nq + (size_t)b * QN * HID;
    const int tid = threadIdx.x;

    for (int s = tid; s < NB2; s += 256) sseg[s] = 0ULL;
    if (tid < 4) stop4[tid] = 0u;
    if (tid < BM) {
        int gi = i0 + tid; sbi[tid] = (gi < QN) ? g_bin[b * QN + gi] : 0;
        int gj = j0 + tid; sbj[tid] = (gj < QN) ? g_bin[b * QN + gj] : 0;
    }

    const int mr = tid & 15, mc = tid >> 4;
    const int ra = mr * 4, cb = mc * 4;

    unsigned long long acc[8][4];
    #pragma unroll
    for (int r = 0; r < 8; r++)
        #pragma unroll
        for (int g = 0; g < 4; g++) acc[r][g] = 0ULL;

    const int lrow0 = tid >> 2,        lkq0 = (tid & 3) << 2;
    const int lrow1 = (tid + 256) >> 2, lkq1 = ((tid + 256) & 3) << 2;
    const bool okA0 = (i0 + lrow0) < QN, okA1 = (i0 + lrow1) < QN;
    const bool okB0 = (j0 + lrow0) < QN, okB1 = (j0 + lrow1) < QN;
    const float* pA0 = nq + (i0 + lrow0) * HID + lkq0;
    const float* pA1 = nq + min(i0 + lrow1, QN - 1) * HID + lkq1;
    const float* pB0 = nq + (j0 + lrow0) * HID + lkq0;
    const float* pB1 = nq + min(j0 + lrow1, QN - 1) * HID + lkq1;

    float4 rA0, rA1, rB0, rB1;
    const float4 z4 = make_float4(0.f, 0.f, 0.f, 0.f);

    // prologue load tile 0
    rA0 = okA0 ? *(const float4*)pA0 : z4;
    rA1 = okA1 ? *(const float4*)pA1 : z4;
    rB0 = okB0 ? *(const float4*)pB0 : z4;
    rB1 = okB1 ? *(const float4*)pB1 : z4;
    {
        As[0][lkq0+0][lrow0]=rA0.x; As[0][lkq0+1][lrow0]=rA0.y; As[0][lkq0+2][lrow0]=rA0.z; As[0][lkq0+3][lrow0]=rA0.w;
        As[0][lkq1+0][lrow1]=rA1.x; As[0][lkq1+1][lrow1]=rA1.y; As[0][lkq1+2][lrow1]=rA1.z; As[0][lkq1+3][lrow1]=rA1.w;
        Bs[0][lkq0+0][lrow0]=rB0.x; Bs[0][lkq0+1][lrow0]=rB0.y; Bs[0][lkq0+2][lrow0]=rB0.z; Bs[0][lkq0+3][lrow0]=rB0.w;
        Bs[0][lkq1+0][lrow1]=rB1.x; Bs[0][lkq1+1][lrow1]=rB1.y; Bs[0][lkq1+2][lrow1]=rB1.z; Bs[0][lkq1+3][lrow1]=rB1.w;
    }
    __syncthreads();

    const int NKT = HID / BK;  // 16
    #pragma unroll 1
    for (int kt = 0; kt < NKT; kt++) {
        const int cur = kt & 1;
        if (kt + 1 < NKT) {
            int off = (kt + 1) * BK;
            rA0 = okA0 ? *(const float4*)(pA0 + off) : z4;
            rA1 = okA1 ? *(const float4*)(pA1 + off) : z4;
            rB0 = okB0 ? *(const float4*)(pB0 + off) : z4;
            rB1 = okB1 ? *(const float4*)(pB1 + off) : z4;
        }
        #pragma unroll
        for (int k = 0; k < BK; k++) {
            float4 a0 = *(const float4*)&As[cur][k][ra];
            float4 a1 = *(const float4*)&As[cur][k][ra + 64];
            ulonglong2 bb0 = *(const ulonglong2*)&Bs[cur][k][cb];
            ulonglong2 bb1 = *(const ulonglong2*)&Bs[cur][k][cb + 64];
            unsigned long long bv0 = bb0.x, bv1 = bb0.y, bv2 = bb1.x, bv3 = bb1.y;
            float av[8] = {a0.x, a0.y, a0.z, a0.w, a1.x, a1.y, a1.z, a1.w};
            #pragma unroll
            for (int r = 0; r < 8; r++) {
                unsigned long long a2 = pack2(av[r]);
                ffma2(acc[r][0], a2, bv0);
                ffma2(acc[r][1], a2, bv1);
                ffma2(acc[r][2], a2, bv2);
                ffma2(acc[r][3], a2, bv3);
            }
        }
        if (kt + 1 < NKT) {
            const int nxt = cur ^ 1;
            As[nxt][lkq0+0][lrow0]=rA0.x; As[nxt][lkq0+1][lrow0]=rA0.y; As[nxt][lkq0+2][lrow0]=rA0.z; As[nxt][lkq0+3][lrow0]=rA0.w;
            As[nxt][lkq1+0][lrow1]=rA1.x; As[nxt][lkq1+1][lrow1]=rA1.y; As[nxt][lkq1+2][lrow1]=rA1.z; As[nxt][lkq1+3][lrow1]=rA1.w;
            Bs[nxt][lkq0+0][lrow0]=rB0.x; Bs[nxt][lkq0+1][lrow0]=rB0.y; Bs[nxt][lkq0+2][lrow0]=rB0.z; Bs[nxt][lkq0+3][lrow0]=rB0.w;
            Bs[nxt][lkq1+0][lrow1]=rB1.x; Bs[nxt][lkq1+1][lrow1]=rB1.y; Bs[nxt][lkq1+2][lrow1]=rB1.z; Bs[nxt][lkq1+3][lrow1]=rB1.w;
            __syncthreads();
        }
    }
    __syncthreads();

    // epilogue: segment argmax + local top4
    unsigned lt[4] = {0u, 0u, 0u, 0u};
    #pragma unroll
    for (int r = 0; r < 8; r++) {
        int lrow = ra + ((r < 4) ? r : (r - 4 + 64));
        int gi = i0 + lrow;
        #pragma unroll
        for (int g = 0; g < 4; g++) {
            int lcol = cb + ((g < 2) ? 2 * g : (2 * (g - 2) + 64));
            float vlo, vhi;
            unpack2(acc[r][g], vlo, vhi);
            #pragma unroll
            for (int h = 0; h < 2; h++) {
                int gj = j0 + lcol + h;
                float v = h ? vhi : vlo;
                if (gi < QN && gj < QN && gi < gj) {
                    unsigned ev = encf(v);
                    if (ev > lt[3]) {
                        if (ev > lt[0])      { lt[3]=lt[2]; lt[2]=lt[1]; lt[1]=lt[0]; lt[0]=ev; }
                        else if (ev > lt[1]) { lt[3]=lt[2]; lt[2]=lt[1]; lt[1]=ev; }
                        else if (ev > lt[2]) { lt[3]=lt[2]; lt[2]=ev; }
                        else                 { lt[3]=ev; }
                    }
                    int bi = sbi[lrow], bj = sbj[lcol + h];
                    int sgm = min(bi, bj) * NBINS + max(bi, bj);
                    unsigned long long key =
                        ((unsigned long long)ev << 32) |
                        (unsigned long long)(0xFFFFFFFFu - (unsigned)(gi * QN + gj));
                    atomicMax(&sseg[sgm], key);
                }
            }
        }
    }
    #pragma unroll
    for (int q4 = 0; q4 < 4; q4++) {
        unsigned v = lt[q4];
        if (!v) break;
        #pragma unroll
        for (int sl = 0; sl < 4; sl++) {
            unsigned old = atomicMax(&stop4[sl], v);
            v = min(v, old);
            if (!v) break;
        }
    }
    __syncthreads();

    unsigned long long* gs = g_seg + (size_t)b * NB2;
    for (int s = tid; s < NB2; s += 256) {
        unsigned long long k = sseg[s];
        if (k) atomicMax(&gs[s], k);
    }
    if (tid == 0) {
        unsigned* gt = g_top4 + b * 4;
        #pragma unroll
        for (int q4 = 0; q4 < 4; q4++) {
            unsigned v = stop4[q4];
            if (!v) continue;
            for (int sl = 0; sl < 4; sl++) {
                unsigned old = atomicMax(&gt[sl], v);
                v = min(v, old);
                if (!v) break;
            }
        }
    }
}

// ---------------- finalize helpers ----------------
__device__ __forceinline__ int blockReduceInt(int v, int* sh, int tid) {
    sh[tid] = v; __syncthreads();
    #pragma unroll
    for (int o = 128; o; o >>= 1) { if (tid < o) sh[tid] += sh[tid + o]; __syncthreads(); }
    int r = sh[0]; __syncthreads();
    return r;
}
__device__ __forceinline__ float blockReduceFloat(float v, float* sh, int tid) {
    sh[tid] = v; __syncthreads();
    #pragma unroll
    for (int o = 128; o; o >>= 1) { if (tid < o) sh[tid] += sh[tid + o]; __syncthreads(); }
    float r = sh[0]; __syncthreads();
    return r;
}
// top-2 (encoded) block reduction
__device__ void top2Block(unsigned m1, unsigned m2, unsigned* r1, unsigned* r2,
                          int tid, unsigned& o1, unsigned& o2) {
    r1[tid] = m1; r2[tid] = m2; __syncthreads();
    #pragma unroll
    for (int o = 128; o; o >>= 1) {
        if (tid < o) {
            unsigned a1 = r1[tid], a2 = r2[tid], b1 = r1[tid + o], b2 = r2[tid + o];
            unsigned n1 = max(a1, b1);
            unsigned n2 = max(min(a1, b1), max(a2, b2));
            r1[tid] = n1; r2[tid] = n2;
        }
        __syncthreads();
    }
    o1 = r1[0]; o2 = r2[0]; __syncthreads();
}
// quantile q=1-1/(n+1) over a sorted masked set given its top-2 values (exact)
__device__ __forceinline__ float quant2(float vmax, float vsec, int n) {
    if (n <= 0) return BIGV;  // sorted[0] would be the BIG pad
    float nf = (float)n;
    float q  = 1.0f - 1.0f / (nf + 1.0f);
    float pos = q * fmaxf(nf - 1.0f, 0.0f);
    int lo = (int)floorf(pos); lo = min(max(lo, 0), NB2 - 1);
    int hi = (int)ceilf(pos);  hi = min(max(hi, 0), NB2 - 1);
    float frac = pos - (float)lo;
    float vlo = (lo >= n - 1) ? vmax : vsec;
    float vhi = (hi >= n - 1) ? vmax : vsec;
    return vlo + (vhi - vlo) * frac;
}

// ---------------- finalize: one block per batch ----------------
__global__ __launch_bounds__(256) void k_final() {
    __shared__ float ssel[NB2], sdd[NB2], sai[NB2], saj[NB2];
    __shared__ unsigned char svld[NB2], smF[NB2];
    __shared__ unsigned r1[256], r2[256];
    __shared__ float redf[256];
    __shared__ int   redi[256];
    __shared__ unsigned hist[256];
    __shared__ unsigned s_dig, s_bef;

    const int tid = threadIdx.x;
    const int b   = blockIdx.x;
    const float* ang = g_ang + b * QN;
    const float TWO_PI_F  = 6.283185307179586f;
    const float HALF_PI_F = 1.5707963267948966f;

    for (int s = tid; s < NB2; s += 256) {
        unsigned long long key = g_seg[(size_t)b * NB2 + s];
        float v = 0.f, ai = 0.f, aj = 0.f, d = 0.f;
        unsigned char vl = 0;
        if (key) {
            vl = 1;
            v = decf((unsigned)(key >> 32));
            unsigned ij = 0xFFFFFFFFu - (unsigned)key;
            int i = ij / QN, j = ij - i * QN;
            ai = ang[i]; aj = ang[j];
            float diff = fabsf(ai - aj);
            d = fminf(fminf(diff, TWO_PI_F - diff), HALF_PI_F);
        }
        ssel[s] = v; sai[s] = ai; saj[s] = aj; sdd[s] = d; svld[s] = vl;
    }
    __syncthreads();

    // S and top-2 of valid sel
    int c = 0; unsigned m1 = 0, m2 = 0;
    for (int s = tid; s < NB2; s += 256) {
        if (svld[s]) {
            c++;
            unsigned e = encf(ssel[s]);
            if (e > m1) { m2 = m1; m1 = e; } else if (e > m2) m2 = e;
        }
    }
    int S = blockReduceInt(c, redi, tid);
    unsigned t1, t2; top2Block(m1, m2, r1, r2, tid, t1, t2);
    float thr = quant2(decf(t1), decf(t2), S);

    // mask1
    c = 0;
    for (int s = tid; s < NB2; s += 256) {
        unsigned char m = (svld[s] && ssel[s] > thr) ? 1 : 0;
        smF[s] = m; c += m;
    }
    int c1 = blockReduceInt(c, redi, tid);

    // fallback
    float th2 = decf(g_top4[b * 4 + 3]);
    bool use_fb = (c1 < 2);
    c = 0;
    for (int s = tid; s < NB2; s += 256) {
        unsigned char m = use_fb ? ((svld[s] && ssel[s] >= th2) ? 1 : 0) : smF[s];
        smF[s] = m; c += m;
    }
    int cnt = blockReduceInt(c, redi, tid);

    // median of masked d: radix select k-th smallest (d >= 0 so uint order = float order)
    float med = BIGV;
    if (cnt > 0) {
        int kk = (cnt - 1) >> 1;
        unsigned prefix = 0;
        for (int shift = 24; shift >= 0; shift -= 8) {
            hist[tid] = 0;
            __syncthreads();
            for (int s = tid; s < NB2; s += 256) {
                if (smF[s]) {
                    unsigned key = __float_as_uint(sdd[s]);
                    bool in = (shift == 24) || ((key >> (shift + 8)) == prefix);
                    if (in) atomicAdd(&hist[(key >> shift) & 255u], 1u);
                }
            }
            __syncthreads();
            if (tid == 0) {
                unsigned cum = 0; unsigned d = 0;
                for (; d < 256; d++) {
                    unsigned h = hist[d];
                    if (cum + h > (unsigned)kk) break;
                    cum += h;
                }
                s_dig = d; s_bef = cum;
            }
            __syncthreads();
            prefix = (prefix << 8) | s_dig;
            kk -= (int)s_bef;
            __syncthreads();
        }
        med = __uint_as_float(prefix);
    }
    float alpha = fminf(fmaxf(med, (float)(3.14159265358979323846 / 36.0)), HALF_PI_F);
    __syncthreads();

    // cooperative loss
    float fs = 0.f; int nc = 0;
    for (int s = tid; s < NB2; s += 256) {
        if (smF[s] && sdd[s] <= alpha) {
            float ai = sai[s], aj = saj[s];
            float mean = atan2f((sinf(ai) + sinf(aj)) * 0.5f,
                                (cosf(ai) + cosf(aj)) * 0.5f);
            float d1 = fabsf(ai - mean); d1 = fminf(fminf(d1, TWO_PI_F - d1), HALF_PI_F);
            float d2 = fabsf(aj - mean); d2 = fminf(fminf(d2, TWO_PI_F - d2), HALF_PI_F);
            fs += d1 * d1 + d2 * d2;
            nc++;
        }
    }
    float coop_sum = blockReduceFloat(fs, redf, tid);
    int n_coop = blockReduceInt(nc, redi, tid);
    float coop_b = coop_sum / (float)max(n_coop, 1);

    // competitive loss: count + top-2 of comp-masked sel
    c = 0; m1 = 0; m2 = 0;
    for (int s = tid; s < NB2; s += 256) {
        if (smF[s] && sdd[s] > alpha) {
            c++;
            unsigned e = encf(ssel[s]);
            if (e > m1) { m2 = m1; m1 = e; } else if (e > m2) m2 = e;
        }
    }
    int n_comp = blockReduceInt(c, redi, tid);
    top2Block(m1, m2, r1, r2, tid, t1, t2);
    float margin = quant2(decf(t1), decf(t2), n_comp);

    fs = 0.f;
    for (int s = tid; s < NB2; s += 256) {
        if (smF[s] && sdd[s] > alpha) {
            float viol = fmaxf(ssel[s] - margin, 0.f);
            fs += viol * viol;
        }
    }
    float comp_sum = blockReduceFloat(fs, redf, tid);
    float comp_b = comp_sum / (float)max(n_comp, 1);

    if (tid == 0) {
        g_res[b * 4 + 0] = coop_b;
        g_res[b * 4 + 1] = comp_b;
        g_res[b * 4 + 2] = (cnt > 0) ? 1.0f : 0.0f;
    }
}

// ---------------- combine ----------------
__global__ void k_out(float* out) {
    if (threadIdx.x == 0 && blockIdx.x == 0) {
        float cs = 0.f, ps = 0.f; int nv = 0;
        for (int b = 0; b < NBATCH; b++) {
            cs += g_res[b * 4 + 0];
            ps += g_res[b * 4 + 1];
            nv += (g_res[b * 4 + 2] > 0.f) ? 1 : 0;
        }
        float denom = (float)max(nv, 1);
        out[0] = cs / denom;
        out[1] = ps / denom;
    }
}

// ---------------- launch ----------------
extern "C" void kernel_launch(void* const* d_in, const int* in_sizes, int n_in,
                              void* d_out, int out_size) {
    const float* qf = (const float*)d_in[0];   // [16,900,256]
    const float* pa = (const float*)d_in[1];   // [16,900,2]
    const float* W  = (const float*)d_in[2];   // [36,256]
    float* out = (float*)d_out;

    k_init<<<(NBATCH * NB2 + 255) / 256, 256>>>();
    k_prep<<<NBATCH * QN, HID>>>(qf, pa, W);
    dim3 g2(NTP2, NBATCH);
    k_pair<<<g2, 256>>>();
    k_final<<<NBATCH, 256>>>();
    k_out<<<1, 32>>>(out);
}

// round 3
// speedup vs baseline: 3.1413x; 1.1029x over previous
#include <cuda_runtime.h>
#include <math.h>

#define NBATCH 16
#define QN 900
#define HID 256
#define NBINS 36
#define NB2 1296
#define BIGV 1e9f

#define BM 128
#define BK 16
#define NTI2 8      // ceil(900/128)
#define NTP2 36     // 8*9/2

// ---------------- device globals ----------------
__device__ float g_nq[NBATCH * QN * HID];
__device__ float g_ang[NBATCH * QN];
__device__ int   g_bin[NBATCH * QN];
__device__ unsigned long long g_seg[NBATCH * NB2];  // (ordfloat<<32)|(~pairidx)
__device__ unsigned int g_top4[NBATCH * 4];
__device__ float g_res[NBATCH * 4];
__device__ unsigned int g_done;

// ---------------- ordered-float encoding ----------------
__device__ __forceinline__ unsigned encf(float f) {
    unsigned u = __float_as_uint(f);
    return (u & 0x80000000u) ? ~u : (u | 0x80000000u);
}
__device__ __forceinline__ float decf(unsigned u) {
    unsigned v = (u & 0x80000000u) ? (u ^ 0x80000000u) : ~u;
    return __uint_as_float(v);
}

// packed f32x2 fma (sm_103a FFMA2 — ptxas never auto-emits this)
__device__ __forceinline__ void ffma2(unsigned long long& d,
                                      unsigned long long a, unsigned long long b) {
    asm("fma.rn.f32x2 %0, %1, %2, %0;" : "+l"(d) : "l"(a), "l"(b));
}
__device__ __forceinline__ unsigned long long pack2(float v) {
    unsigned long long r;
    asm("mov.b64 %0, {%1, %1};" : "=l"(r) : "f"(v));
    return r;
}
__device__ __forceinline__ void unpack2(unsigned long long p, float& lo, float& hi) {
    asm("mov.b64 {%0, %1}, %2;" : "=f"(lo), "=f"(hi) : "l"(p));
}

// ---------------- prep (+ table init): warp per query ----------------
__global__ __launch_bounds__(256) void k_prep(const float* __restrict__ qf,
                                              const float* __restrict__ pa,
                                              const float* __restrict__ W) {
    int gid = blockIdx.x * 256 + threadIdx.x;
    if (gid < NBATCH * NB2) g_seg[gid] = 0ULL;
    if (gid < NBATCH * 4)   g_top4[gid] = 0u;
    if (gid == 0)           g_done = 0u;

    const int warp = threadIdx.x >> 5;
    const int lane = threadIdx.x & 31;
    const int bq = blockIdx.x * 8 + warp;   // grid = 1800 -> exact 14400

    int bin = 0;
    if (lane == 0) {
        float x = pa[bq * 2 + 0], y = pa[bq * 2 + 1];
        float a = (float)atan2((double)y, (double)x);
        const float TWO_PI_F = 6.283185307179586f;
        if (a < 0.0f) a += TWO_PI_F;
        const float BIN_SIZE_F = (float)(6.283185307179586476925287 / 36.0);
        bin = (int)(a / BIN_SIZE_F);
        bin = min(max(bin, 0), NBINS - 1);
        g_ang[bq] = a; g_bin[bq] = bin;
    }
    bin = __shfl_sync(0xffffffffu, bin, 0);

    const float4* qr = (const float4*)(qf + (size_t)bq * HID);
    const float4* wr = (const float4*)(W + (size_t)bin * HID);
    float4 f0 = qr[lane], f1 = qr[lane + 32];
    float4 w0 = wr[lane], w1 = wr[lane + 32];
    f0.x += w0.x; f0.y += w0.y; f0.z += w0.z; f0.w += w0.w;
    f1.x += w1.x; f1.y += w1.y; f1.z += w1.z; f1.w += w1.w;
    float ss = f0.x*f0.x + f0.y*f0.y + f0.z*f0.z + f0.w*f0.w
             + f1.x*f1.x + f1.y*f1.y + f1.z*f1.z + f1.w*f1.w;
    #pragma unroll
    for (int o = 16; o; o >>= 1) ss += __shfl_xor_sync(0xffffffffu, ss, o);
    float nrm = fmaxf(sqrtf(ss), 1e-12f);

    float4* dst = (float4*)(g_nq + (size_t)bq * HID);
    float4 o0, o1;
    o0.x = f0.x / nrm; o0.y = f0.y / nrm; o0.z = f0.z / nrm; o0.w = f0.w / nrm;
    o1.x = f1.x / nrm; o1.y = f1.y / nrm; o1.z = f1.z / nrm; o1.w = f1.w / nrm;
    dst[lane] = o0; dst[lane + 32] = o1;
}

// ---------------- pair kernel: 128x128 FFMA2 GEMM + segment argmax ----------------
__global__ __launch_bounds__(256, 2) void k_pair() {
    __shared__ __align__(16) float As[2][BK][BM + 4];
    __shared__ __align__(16) float Bs[2][BK][BM + 4];
    __shared__ unsigned long long sseg[NB2];
    __shared__ int sbi[BM], sbj[BM];
    __shared__ unsigned stop4[4];

    const int b = blockIdx.y;
    int p = blockIdx.x;
    int ti = 0, rem = p;
    while (rem >= NTI2 - ti) { rem -= NTI2 - ti; ti++; }
    const int tj = ti + rem;
    const int i0 = ti * BM, j0 = tj * BM;

    const float* __restrict__ nq = g_nq + (size_t)b * QN * HID;
    const int tid = threadIdx.x;

    for (int s = tid; s < NB2; s += 256) sseg[s] = 0ULL;
    if (tid < 4) stop4[tid] = 0u;
    if (tid < BM) {
        int gi = i0 + tid; sbi[tid] = (gi < QN) ? g_bin[b * QN + gi] : 0;
        int gj = j0 + tid; sbj[tid] = (gj < QN) ? g_bin[b * QN + gj] : 0;
    }

    const int mr = tid & 15, mc = tid >> 4;
    const int ra = mr * 4, cb = mc * 4;

    unsigned long long acc[8][4];
    #pragma unroll
    for (int r = 0; r < 8; r++)
        #pragma unroll
        for (int g = 0; g < 4; g++) acc[r][g] = 0ULL;

    const int lrow0 = tid >> 2,        lkq0 = (tid & 3) << 2;
    const int lrow1 = (tid + 256) >> 2, lkq1 = ((tid + 256) & 3) << 2;
    const bool okA0 = (i0 + lrow0) < QN, okA1 = (i0 + lrow1) < QN;
    const bool okB0 = (j0 + lrow0) < QN, okB1 = (j0 + lrow1) < QN;
    const float* pA0 = nq + (i0 + lrow0) * HID + lkq0;
    const float* pA1 = nq + min(i0 + lrow1, QN - 1) * HID + lkq1;
    const float* pB0 = nq + (j0 + lrow0) * HID + lkq0;
    const float* pB1 = nq + min(j0 + lrow1, QN - 1) * HID + lkq1;

    float4 rA0, rA1, rB0, rB1;
    const float4 z4 = make_float4(0.f, 0.f, 0.f, 0.f);

    rA0 = okA0 ? *(const float4*)pA0 : z4;
    rA1 = okA1 ? *(const float4*)pA1 : z4;
    rB0 = okB0 ? *(const float4*)pB0 : z4;
    rB1 = okB1 ? *(const float4*)pB1 : z4;
    {
        As[0][lkq0+0][lrow0]=rA0.x; As[0][lkq0+1][lrow0]=rA0.y; As[0][lkq0+2][lrow0]=rA0.z; As[0][lkq0+3][lrow0]=rA0.w;
        As[0][lkq1+0][lrow1]=rA1.x; As[0][lkq1+1][lrow1]=rA1.y; As[0][lkq1+2][lrow1]=rA1.z; As[0][lkq1+3][lrow1]=rA1.w;
        Bs[0][lkq0+0][lrow0]=rB0.x; Bs[0][lkq0+1][lrow0]=rB0.y; Bs[0][lkq0+2][lrow0]=rB0.z; Bs[0][lkq0+3][lrow0]=rB0.w;
        Bs[0][lkq1+0][lrow1]=rB1.x; Bs[0][lkq1+1][lrow1]=rB1.y; Bs[0][lkq1+2][lrow1]=rB1.z; Bs[0][lkq1+3][lrow1]=rB1.w;
    }
    __syncthreads();

    const int NKT = HID / BK;  // 16
    #pragma unroll 1
    for (int kt = 0; kt < NKT; kt++) {
        const int cur = kt & 1;
        if (kt + 1 < NKT) {
            int off = (kt + 1) * BK;
            rA0 = okA0 ? *(const float4*)(pA0 + off) : z4;
            rA1 = okA1 ? *(const float4*)(pA1 + off) : z4;
            rB0 = okB0 ? *(const float4*)(pB0 + off) : z4;
            rB1 = okB1 ? *(const float4*)(pB1 + off) : z4;
        }
        #pragma unroll
        for (int k = 0; k < BK; k++) {
            float4 a0 = *(const float4*)&As[cur][k][ra];
            float4 a1 = *(const float4*)&As[cur][k][ra + 64];
            ulonglong2 bb0 = *(const ulonglong2*)&Bs[cur][k][cb];
            ulonglong2 bb1 = *(const ulonglong2*)&Bs[cur][k][cb + 64];
            unsigned long long bv0 = bb0.x, bv1 = bb0.y, bv2 = bb1.x, bv3 = bb1.y;
            float av[8] = {a0.x, a0.y, a0.z, a0.w, a1.x, a1.y, a1.z, a1.w};
            #pragma unroll
            for (int r = 0; r < 8; r++) {
                unsigned long long a2 = pack2(av[r]);
                ffma2(acc[r][0], a2, bv0);
                ffma2(acc[r][1], a2, bv1);
                ffma2(acc[r][2], a2, bv2);
                ffma2(acc[r][3], a2, bv3);
            }
        }
        if (kt + 1 < NKT) {
            const int nxt = cur ^ 1;
            As[nxt][lkq0+0][lrow0]=rA0.x; As[nxt][lkq0+1][lrow0]=rA0.y; As[nxt][lkq0+2][lrow0]=rA0.z; As[nxt][lkq0+3][lrow0]=rA0.w;
            As[nxt][lkq1+0][lrow1]=rA1.x; As[nxt][lkq1+1][lrow1]=rA1.y; As[nxt][lkq1+2][lrow1]=rA1.z; As[nxt][lkq1+3][lrow1]=rA1.w;
            Bs[nxt][lkq0+0][lrow0]=rB0.x; Bs[nxt][lkq0+1][lrow0]=rB0.y; Bs[nxt][lkq0+2][lrow0]=rB0.z; Bs[nxt][lkq0+3][lrow0]=rB0.w;
            Bs[nxt][lkq1+0][lrow1]=rB1.x; Bs[nxt][lkq1+1][lrow1]=rB1.y; Bs[nxt][lkq1+2][lrow1]=rB1.z; Bs[nxt][lkq1+3][lrow1]=rB1.w;
            __syncthreads();
        }
    }
    __syncthreads();

    // epilogue: segment argmax (read-before-atomic) + local top4
    unsigned lt[4] = {0u, 0u, 0u, 0u};
    #pragma unroll
    for (int r = 0; r < 8; r++) {
        int lrow = ra + ((r < 4) ? r : (r - 4 + 64));
        int gi = i0 + lrow;
        #pragma unroll
        for (int g = 0; g < 4; g++) {
            int lcol = cb + ((g < 2) ? 2 * g : (2 * (g - 2) + 64));
            float vlo, vhi;
            unpack2(acc[r][g], vlo, vhi);
            #pragma unroll
            for (int h = 0; h < 2; h++) {
                int gj = j0 + lcol + h;
                float v = h ? vhi : vlo;
                if (gi < QN && gj < QN && gi < gj) {
                    unsigned ev = encf(v);
                    if (ev > lt[3]) {
                        if (ev > lt[0])      { lt[3]=lt[2]; lt[2]=lt[1]; lt[1]=lt[0]; lt[0]=ev; }
                        else if (ev > lt[1]) { lt[3]=lt[2]; lt[2]=lt[1]; lt[1]=ev; }
                        else if (ev > lt[2]) { lt[3]=lt[2]; lt[2]=ev; }
                        else                 { lt[3]=ev; }
                    }
                    int bi = sbi[lrow], bj = sbj[lcol + h];
                    int sgm = min(bi, bj) * NBINS + max(bi, bj);
                    unsigned long long key =
                        ((unsigned long long)ev << 32) |
                        (unsigned long long)(0xFFFFFFFFu - (unsigned)(gi * QN + gj));
                    if (key > sseg[sgm]) atomicMax(&sseg[sgm], key);
                }
            }
        }
    }
    #pragma unroll
    for (int q4 = 0; q4 < 4; q4++) {
        unsigned v = lt[q4];
        if (!v) break;
        #pragma unroll
        for (int sl = 0; sl < 4; sl++) {
            if (v > stop4[sl]) {
                unsigned old = atomicMax(&stop4[sl], v);
                v = min(v, old);
            }
            if (!v) break;
        }
    }
    __syncthreads();

    unsigned long long* gs = g_seg + (size_t)b * NB2;
    for (int s = tid; s < NB2; s += 256) {
        unsigned long long k = sseg[s];
        if (k && k > gs[s]) atomicMax(&gs[s], k);
    }
    if (tid == 0) {
        unsigned* gt = g_top4 + b * 4;
        #pragma unroll
        for (int q4 = 0; q4 < 4; q4++) {
            unsigned v = stop4[q4];
            if (!v) continue;
            for (int sl = 0; sl < 4; sl++) {
                if (v > gt[sl]) {
                    unsigned old = atomicMax(&gt[sl], v);
                    v = min(v, old);
                }
                if (!v) break;
            }
        }
    }
}

// ---------------- finalize helpers (shfl-based, few syncs) ----------------
__device__ __forceinline__ float bsumf(float v, float* sh8, int tid) {
    #pragma unroll
    for (int o = 16; o; o >>= 1) v += __shfl_xor_sync(0xffffffffu, v, o);
    if ((tid & 31) == 0) sh8[tid >> 5] = v;
    __syncthreads();
    float r = sh8[0]+sh8[1]+sh8[2]+sh8[3]+sh8[4]+sh8[5]+sh8[6]+sh8[7];
    __syncthreads();
    return r;
}
__device__ __forceinline__ int bsumi(int v, int* sh8, int tid) {
    #pragma unroll
    for (int o = 16; o; o >>= 1) v += __shfl_xor_sync(0xffffffffu, v, o);
    if ((tid & 31) == 0) sh8[tid >> 5] = v;
    __syncthreads();
    int r = sh8[0]+sh8[1]+sh8[2]+sh8[3]+sh8[4]+sh8[5]+sh8[6]+sh8[7];
    __syncthreads();
    return r;
}
__device__ __forceinline__ void btop2(unsigned m1, unsigned m2,
                                      unsigned* s1, unsigned* s2, int tid,
                                      unsigned& o1, unsigned& o2) {
    #pragma unroll
    for (int o = 16; o; o >>= 1) {
        unsigned u1 = __shfl_xor_sync(0xffffffffu, m1, o);
        unsigned u2 = __shfl_xor_sync(0xffffffffu, m2, o);
        unsigned n1 = max(m1, u1);
        unsigned n2 = max(min(m1, u1), max(m2, u2));
        m1 = n1; m2 = n2;
    }
    if ((tid & 31) == 0) { s1[tid >> 5] = m1; s2[tid >> 5] = m2; }
    __syncthreads();
    unsigned t1 = 0, t2 = 0;
    #pragma unroll
    for (int w = 0; w < 8; w++) {
        unsigned a = s1[w], b = s2[w];
        if (a > t1) { t2 = max(t1, b); t1 = a; }
        else { t2 = max(t2, a); }
        (void)b;
        if (a <= t1 && a != t1) {}  // no-op
    }
    // redo merge properly (t2 handling): recompute cleanly
    t1 = 0; t2 = 0;
    #pragma unroll
    for (int w = 0; w < 8; w++) {
        unsigned a = s1[w], b = s2[w];
        unsigned n1 = max(t1, a);
        unsigned n2 = max(min(t1, a), max(t2, b));
        t1 = n1; t2 = n2;
    }
    __syncthreads();
    o1 = t1; o2 = t2;
}
__device__ __forceinline__ float quant2(float vmax, float vsec, int n) {
    if (n <= 0) return BIGV;
    float nf = (float)n;
    float q  = 1.0f - 1.0f / (nf + 1.0f);
    float pos = q * fmaxf(nf - 1.0f, 0.0f);
    int lo = (int)floorf(pos); lo = min(max(lo, 0), NB2 - 1);
    int hi = (int)ceilf(pos);  hi = min(max(hi, 0), NB2 - 1);
    float frac = pos - (float)lo;
    float vlo = (lo >= n - 1) ? vmax : vsec;
    float vhi = (hi >= n - 1) ? vmax : vsec;
    return vlo + (vhi - vlo) * frac;
}

// ---------------- finalize (+ combine): one block per batch ----------------
__global__ __launch_bounds__(256) void k_final(float* __restrict__ out) {
    __shared__ float ssel[NB2], sdd[NB2], sai[NB2], saj[NB2];
    __shared__ unsigned char svld[NB2], smF[NB2];
    __shared__ float shf[8];
    __shared__ int   shi[8];
    __shared__ unsigned sh1[8], sh2[8];
    __shared__ unsigned hist[256], scn[256];
    __shared__ unsigned s_dig, s_bef;
    __shared__ int s_last;

    const int tid = threadIdx.x;
    const int b   = blockIdx.x;
    const float* ang = g_ang + b * QN;
    const float TWO_PI_F  = 6.283185307179586f;
    const float HALF_PI_F = 1.5707963267948966f;

    for (int s = tid; s < NB2; s += 256) {
        unsigned long long key = g_seg[(size_t)b * NB2 + s];
        float v = 0.f, ai = 0.f, aj = 0.f, d = 0.f;
        unsigned char vl = 0;
        if (key) {
            vl = 1;
            v = decf((unsigned)(key >> 32));
            unsigned ij = 0xFFFFFFFFu - (unsigned)key;
            int i = ij / QN, j = ij - i * QN;
            ai = ang[i]; aj = ang[j];
            float diff = fabsf(ai - aj);
            d = fminf(fminf(diff, TWO_PI_F - diff), HALF_PI_F);
        }
        ssel[s] = v; sai[s] = ai; saj[s] = aj; sdd[s] = d; svld[s] = vl;
    }
    __syncthreads();

    // S and top-2 of valid sel
    int c = 0; unsigned m1 = 0, m2 = 0;
    for (int s = tid; s < NB2; s += 256) {
        if (svld[s]) {
            c++;
            unsigned e = encf(ssel[s]);
            if (e > m1) { m2 = m1; m1 = e; } else if (e > m2) m2 = e;
        }
    }
    int S = bsumi(c, shi, tid);
    unsigned t1, t2; btop2(m1, m2, sh1, sh2, tid, t1, t2);
    float thr = quant2(decf(t1), decf(t2), S);

    // mask1
    c = 0;
    for (int s = tid; s < NB2; s += 256) {
        unsigned char m = (svld[s] && ssel[s] > thr) ? 1 : 0;
        smF[s] = m; c += m;
    }
    int c1 = bsumi(c, shi, tid);

    // fallback
    float th2 = decf(g_top4[b * 4 + 3]);
    bool use_fb = (c1 < 2);
    c = 0;
    for (int s = tid; s < NB2; s += 256) {
        unsigned char m = use_fb ? ((svld[s] && ssel[s] >= th2) ? 1 : 0) : smF[s];
        smF[s] = m; c += m;
    }
    int cnt = bsumi(c, shi, tid);

    // median of masked d via radix-select (parallel digit select)
    float med = BIGV;
    if (cnt > 0) {
        int kk = (cnt - 1) >> 1;
        unsigned prefix = 0;
        #pragma unroll
        for (int shift = 24; shift >= 0; shift -= 8) {
            hist[tid] = 0;
            __syncthreads();
            for (int s = tid; s < NB2; s += 256) {
                if (smF[s]) {
                    unsigned key = __float_as_uint(sdd[s]);
                    bool in = (shift == 24) || ((key >> (shift + 8)) == prefix);
                    if (in) atomicAdd(&hist[(key >> shift) & 255u], 1u);
                }
            }
            __syncthreads();
            unsigned my = hist[tid];
            scn[tid] = my;
            __syncthreads();
            #pragma unroll
            for (int off = 1; off < 256; off <<= 1) {
                unsigned v = scn[tid];
                unsigned u = (tid >= off) ? scn[tid - off] : 0u;
                __syncthreads();
                scn[tid] = v + u;
                __syncthreads();
            }
            unsigned cum = scn[tid], bef = cum - my;
            if ((int)cum > kk && (int)bef <= kk) { s_dig = (unsigned)tid; s_bef = bef; }
            __syncthreads();
            prefix = (prefix << 8) | s_dig;
            kk -= (int)s_bef;
            __syncthreads();
        }
        med = __uint_as_float(prefix);
    }
    float alpha = fminf(fmaxf(med, (float)(3.14159265358979323846 / 36.0)), HALF_PI_F);
    __syncthreads();

    // cooperative loss
    float fs = 0.f; int nc = 0;
    for (int s = tid; s < NB2; s += 256) {
        if (smF[s] && sdd[s] <= alpha) {
            float ai = sai[s], aj = saj[s];
            float mean = atan2f((sinf(ai) + sinf(aj)) * 0.5f,
                                (cosf(ai) + cosf(aj)) * 0.5f);
            float d1 = fabsf(ai - mean); d1 = fminf(fminf(d1, TWO_PI_F - d1), HALF_PI_F);
            float d2 = fabsf(aj - mean); d2 = fminf(fminf(d2, TWO_PI_F - d2), HALF_PI_F);
            fs += d1 * d1 + d2 * d2;
            nc++;
        }
    }
    float coop_sum = bsumf(fs, shf, tid);
    int n_coop = bsumi(nc, shi, tid);
    float coop_b = coop_sum / (float)max(n_coop, 1);

    // competitive loss
    c = 0; m1 = 0; m2 = 0;
    for (int s = tid; s < NB2; s += 256) {
        if (smF[s] && sdd[s] > alpha) {
            c++;
            unsigned e = encf(ssel[s]);
            if (e > m1) { m2 = m1; m1 = e; } else if (e > m2) m2 = e;
        }
    }
    int n_comp = bsumi(c, shi, tid);
    btop2(m1, m2, sh1, sh2, tid, t1, t2);
    float margin = quant2(decf(t1), decf(t2), n_comp);

    fs = 0.f;
    for (int s = tid; s < NB2; s += 256) {
        if (smF[s] && sdd[s] > alpha) {
            float viol = fmaxf(ssel[s] - margin, 0.f);
            fs += viol * viol;
        }
    }
    float comp_sum = bsumf(fs, shf, tid);
    float comp_b = comp_sum / (float)max(n_comp, 1);

    if (tid == 0) {
        g_res[b * 4 + 0] = coop_b;
        g_res[b * 4 + 1] = comp_b;
        g_res[b * 4 + 2] = (cnt > 0) ? 1.0f : 0.0f;
        __threadfence();
        unsigned old = atomicAdd(&g_done, 1u);
        s_last = (old == NBATCH - 1) ? 1 : 0;
    }
    __syncthreads();
    if (s_last && tid == 0) {
        __threadfence();
        float cs = 0.f, ps = 0.f; int nv = 0;
        for (int bb = 0; bb < NBATCH; bb++) {
            cs += g_res[bb * 4 + 0];
            ps += g_res[bb * 4 + 1];
            nv += (g_res[bb * 4 + 2] > 0.f) ? 1 : 0;
        }
        float denom = (float)max(nv, 1);
        out[0] = cs / denom;
        out[1] = ps / denom;
    }
}

// ---------------- launch ----------------
extern "C" void kernel_launch(void* const* d_in, const int* in_sizes, int n_in,
                              void* d_out, int out_size) {
    const float* qf = (const float*)d_in[0];   // [16,900,256]
    const float* pa = (const float*)d_in[1];   // [16,900,2]
    const float* W  = (const float*)d_in[2];   // [36,256]
    float* out = (float*)d_out;

    k_prep<<<NBATCH * QN / 8, 256>>>(qf, pa, W);
    dim3 g2(NTP2, NBATCH);
    k_pair<<<g2, 256>>>();
    k_final<<<NBATCH, 256>>>(out);
}

// round 4
// speedup vs baseline: 3.7782x; 1.2027x over previous
#include <cuda_runtime.h>
#include <math.h>

#define NBATCH 16
#define QN 900
#define HID 256
#define NBINS 36
#define NB2 1296
#define BIGV 1e9f

#define BM 128
#define BK 16
#define NTI2 8      // ceil(900/128)
#define NTP2 36     // 8*9/2

// ---------------- device globals ----------------
__device__ float g_nq[NBATCH * QN * HID];
__device__ float g_ang[NBATCH * QN];
__device__ int   g_bin[NBATCH * QN];
__device__ unsigned long long g_seg[NBATCH * NB2];  // (ordfloat<<32)|(~pairidx)
__device__ unsigned int g_top4[NBATCH * 4];
__device__ float g_res[NBATCH * 4];
__device__ unsigned int g_done;

// ---------------- ordered-float encoding ----------------
__device__ __forceinline__ unsigned encf(float f) {
    unsigned u = __float_as_uint(f);
    return (u & 0x80000000u) ? ~u : (u | 0x80000000u);
}
__device__ __forceinline__ float decf(unsigned u) {
    unsigned v = (u & 0x80000000u) ? (u ^ 0x80000000u) : ~u;
    return __uint_as_float(v);
}

// packed f32x2 fma (sm_103a FFMA2 — ptxas never auto-emits this)
__device__ __forceinline__ void ffma2(unsigned long long& d,
                                      unsigned long long a, unsigned long long b) {
    asm("fma.rn.f32x2 %0, %1, %2, %0;" : "+l"(d) : "l"(a), "l"(b));
}
__device__ __forceinline__ unsigned long long pack2(float v) {
    unsigned long long r;
    asm("mov.b64 %0, {%1, %1};" : "=l"(r) : "f"(v));
    return r;
}
__device__ __forceinline__ void unpack2(unsigned long long p, float& lo, float& hi) {
    asm("mov.b64 {%0, %1}, %2;" : "=f"(lo), "=f"(hi) : "l"(p));
}

// ---------------- bins: one thread per query (parallel fp64 atan2) + init ----------------
__global__ __launch_bounds__(256) void k_bins(const float* __restrict__ pa) {
    int gid = blockIdx.x * 256 + threadIdx.x;   // grid = 81*256 = 20736 = NBATCH*NB2
    g_seg[gid] = 0ULL;
    if (gid < NBATCH * 4) g_top4[gid] = 0u;
    if (gid == 0)         g_done = 0u;

    if (gid < NBATCH * QN) {
        float x = pa[gid * 2 + 0], y = pa[gid * 2 + 1];
        float a = (float)atan2((double)y, (double)x);
        const float TWO_PI_F = 6.283185307179586f;
        if (a < 0.0f) a += TWO_PI_F;
        const float BIN_SIZE_F = (float)(6.283185307179586476925287 / 36.0);
        int bin = (int)(a / BIN_SIZE_F);
        bin = min(max(bin, 0), NBINS - 1);
        g_ang[gid] = a; g_bin[gid] = bin;
    }
}

// ---------------- fuse + normalize: pure streaming, warp per query ----------------
__global__ __launch_bounds__(256) void k_fuse(const float* __restrict__ qf,
                                              const float* __restrict__ W) {
    const int warp = threadIdx.x >> 5;
    const int lane = threadIdx.x & 31;
    const int bq = blockIdx.x * 8 + warp;   // grid = 1800 -> exact 14400

    const int bin = g_bin[bq];

    const float4* qr = (const float4*)(qf + (size_t)bq * HID);
    const float4* wr = (const float4*)(W + (size_t)bin * HID);
    float4 f0 = qr[lane], f1 = qr[lane + 32];
    float4 w0 = wr[lane], w1 = wr[lane + 32];
    f0.x += w0.x; f0.y += w0.y; f0.z += w0.z; f0.w += w0.w;
    f1.x += w1.x; f1.y += w1.y; f1.z += w1.z; f1.w += w1.w;
    float ss = f0.x*f0.x + f0.y*f0.y + f0.z*f0.z + f0.w*f0.w
             + f1.x*f1.x + f1.y*f1.y + f1.z*f1.z + f1.w*f1.w;
    #pragma unroll
    for (int o = 16; o; o >>= 1) ss += __shfl_xor_sync(0xffffffffu, ss, o);
    float nrm = fmaxf(sqrtf(ss), 1e-12f);

    float4* dst = (float4*)(g_nq + (size_t)bq * HID);
    float4 o0, o1;
    o0.x = f0.x / nrm; o0.y = f0.y / nrm; o0.z = f0.z / nrm; o0.w = f0.w / nrm;
    o1.x = f1.x / nrm; o1.y = f1.y / nrm; o1.z = f1.z / nrm; o1.w = f1.w / nrm;
    dst[lane] = o0; dst[lane + 32] = o1;
}

// ---------------- pair kernel: 128x128 FFMA2 GEMM + segment argmax ----------------
__global__ __launch_bounds__(256, 2) void k_pair() {
    __shared__ __align__(16) float As[2][BK][BM + 4];
    __shared__ __align__(16) float Bs[2][BK][BM + 4];
    __shared__ unsigned long long sseg[NB2];
    __shared__ int sbi[BM], sbj[BM];
    __shared__ unsigned stop4[4];

    const int b = blockIdx.y;
    int p = blockIdx.x;
    int ti = 0, rem = p;
    while (rem >= NTI2 - ti) { rem -= NTI2 - ti; ti++; }
    const int tj = ti + rem;
    const int i0 = ti * BM, j0 = tj * BM;

    const float* __restrict__ nq = g_nq + (size_t)b * QN * HID;
    const int tid = threadIdx.x;

    for (int s = tid; s < NB2; s += 256) sseg[s] = 0ULL;
    if (tid < 4) stop4[tid] = 0u;
    if (tid < BM) {
        int gi = i0 + tid; sbi[tid] = (gi < QN) ? g_bin[b * QN + gi] : 0;
        int gj = j0 + tid; sbj[tid] = (gj < QN) ? g_bin[b * QN + gj] : 0;
    }

    const int mr = tid & 15, mc = tid >> 4;
    const int ra = mr * 4, cb = mc * 4;

    unsigned long long acc[8][4];
    #pragma unroll
    for (int r = 0; r < 8; r++)
        #pragma unroll
        for (int g = 0; g < 4; g++) acc[r][g] = 0ULL;

    const int lrow0 = tid >> 2,        lkq0 = (tid & 3) << 2;
    const int lrow1 = (tid + 256) >> 2, lkq1 = ((tid + 256) & 3) << 2;
    const bool okA0 = (i0 + lrow0) < QN, okA1 = (i0 + lrow1) < QN;
    const bool okB0 = (j0 + lrow0) < QN, okB1 = (j0 + lrow1) < QN;
    const float* pA0 = nq + (i0 + lrow0) * HID + lkq0;
    const float* pA1 = nq + min(i0 + lrow1, QN - 1) * HID + lkq1;
    const float* pB0 = nq + (j0 + lrow0) * HID + lkq0;
    const float* pB1 = nq + min(j0 + lrow1, QN - 1) * HID + lkq1;

    float4 rA0, rA1, rB0, rB1;
    const float4 z4 = make_float4(0.f, 0.f, 0.f, 0.f);

    rA0 = okA0 ? *(const float4*)pA0 : z4;
    rA1 = okA1 ? *(const float4*)pA1 : z4;
    rB0 = okB0 ? *(const float4*)pB0 : z4;
    rB1 = okB1 ? *(const float4*)pB1 : z4;
    {
        As[0][lkq0+0][lrow0]=rA0.x; As[0][lkq0+1][lrow0]=rA0.y; As[0][lkq0+2][lrow0]=rA0.z; As[0][lkq0+3][lrow0]=rA0.w;
        As[0][lkq1+0][lrow1]=rA1.x; As[0][lkq1+1][lrow1]=rA1.y; As[0][lkq1+2][lrow1]=rA1.z; As[0][lkq1+3][lrow1]=rA1.w;
        Bs[0][lkq0+0][lrow0]=rB0.x; Bs[0][lkq0+1][lrow0]=rB0.y; Bs[0][lkq0+2][lrow0]=rB0.z; Bs[0][lkq0+3][lrow0]=rB0.w;
        Bs[0][lkq1+0][lrow1]=rB1.x; Bs[0][lkq1+1][lrow1]=rB1.y; Bs[0][lkq1+2][lrow1]=rB1.z; Bs[0][lkq1+3][lrow1]=rB1.w;
    }
    __syncthreads();

    const int NKT = HID / BK;  // 16
    #pragma unroll 1
    for (int kt = 0; kt < NKT; kt++) {
        const int cur = kt & 1;
        if (kt + 1 < NKT) {
            int off = (kt + 1) * BK;
            rA0 = okA0 ? *(const float4*)(pA0 + off) : z4;
            rA1 = okA1 ? *(const float4*)(pA1 + off) : z4;
            rB0 = okB0 ? *(const float4*)(pB0 + off) : z4;
            rB1 = okB1 ? *(const float4*)(pB1 + off) : z4;
        }
        #pragma unroll
        for (int k = 0; k < BK; k++) {
            float4 a0 = *(const float4*)&As[cur][k][ra];
            float4 a1 = *(const float4*)&As[cur][k][ra + 64];
            ulonglong2 bb0 = *(const ulonglong2*)&Bs[cur][k][cb];
            ulonglong2 bb1 = *(const ulonglong2*)&Bs[cur][k][cb + 64];
            unsigned long long bv0 = bb0.x, bv1 = bb0.y, bv2 = bb1.x, bv3 = bb1.y;
            float av[8] = {a0.x, a0.y, a0.z, a0.w, a1.x, a1.y, a1.z, a1.w};
            #pragma unroll
            for (int r = 0; r < 8; r++) {
                unsigned long long a2 = pack2(av[r]);
                ffma2(acc[r][0], a2, bv0);
                ffma2(acc[r][1], a2, bv1);
                ffma2(acc[r][2], a2, bv2);
                ffma2(acc[r][3], a2, bv3);
            }
        }
        if (kt + 1 < NKT) {
            const int nxt = cur ^ 1;
            As[nxt][lkq0+0][lrow0]=rA0.x; As[nxt][lkq0+1][lrow0]=rA0.y; As[nxt][lkq0+2][lrow0]=rA0.z; As[nxt][lkq0+3][lrow0]=rA0.w;
            As[nxt][lkq1+0][lrow1]=rA1.x; As[nxt][lkq1+1][lrow1]=rA1.y; As[nxt][lkq1+2][lrow1]=rA1.z; As[nxt][lkq1+3][lrow1]=rA1.w;
            Bs[nxt][lkq0+0][lrow0]=rB0.x; Bs[nxt][lkq0+1][lrow0]=rB0.y; Bs[nxt][lkq0+2][lrow0]=rB0.z; Bs[nxt][lkq0+3][lrow0]=rB0.w;
            Bs[nxt][lkq1+0][lrow1]=rB1.x; Bs[nxt][lkq1+1][lrow1]=rB1.y; Bs[nxt][lkq1+2][lrow1]=rB1.z; Bs[nxt][lkq1+3][lrow1]=rB1.w;
            __syncthreads();
        }
    }
    __syncthreads();

    // epilogue: segment argmax (read-before-atomic) + local top4
    unsigned lt[4] = {0u, 0u, 0u, 0u};
    #pragma unroll
    for (int r = 0; r < 8; r++) {
        int lrow = ra + ((r < 4) ? r : (r - 4 + 64));
        int gi = i0 + lrow;
        #pragma unroll
        for (int g = 0; g < 4; g++) {
            int lcol = cb + ((g < 2) ? 2 * g : (2 * (g - 2) + 64));
            float vlo, vhi;
            unpack2(acc[r][g], vlo, vhi);
            #pragma unroll
            for (int h = 0; h < 2; h++) {
                int gj = j0 + lcol + h;
                float v = h ? vhi : vlo;
                if (gi < QN && gj < QN && gi < gj) {
                    unsigned ev = encf(v);
                    if (ev > lt[3]) {
                        if (ev > lt[0])      { lt[3]=lt[2]; lt[2]=lt[1]; lt[1]=lt[0]; lt[0]=ev; }
                        else if (ev > lt[1]) { lt[3]=lt[2]; lt[2]=lt[1]; lt[1]=ev; }
                        else if (ev > lt[2]) { lt[3]=lt[2]; lt[2]=ev; }
                        else                 { lt[3]=ev; }
                    }
                    int bi = sbi[lrow], bj = sbj[lcol + h];
                    int sgm = min(bi, bj) * NBINS + max(bi, bj);
                    unsigned long long key =
                        ((unsigned long long)ev << 32) |
                        (unsigned long long)(0xFFFFFFFFu - (unsigned)(gi * QN + gj));
                    if (key > sseg[sgm]) atomicMax(&sseg[sgm], key);
                }
            }
        }
    }
    #pragma unroll
    for (int q4 = 0; q4 < 4; q4++) {
        unsigned v = lt[q4];
        if (!v) break;
        #pragma unroll
        for (int sl = 0; sl < 4; sl++) {
            if (v > stop4[sl]) {
                unsigned old = atomicMax(&stop4[sl], v);
                v = min(v, old);
            }
            if (!v) break;
        }
    }
    __syncthreads();

    unsigned long long* gs = g_seg + (size_t)b * NB2;
    for (int s = tid; s < NB2; s += 256) {
        unsigned long long k = sseg[s];
        if (k && k > gs[s]) atomicMax(&gs[s], k);
    }
    if (tid == 0) {
        unsigned* gt = g_top4 + b * 4;
        #pragma unroll
        for (int q4 = 0; q4 < 4; q4++) {
            unsigned v = stop4[q4];
            if (!v) continue;
            for (int sl = 0; sl < 4; sl++) {
                if (v > gt[sl]) {
                    unsigned old = atomicMax(&gt[sl], v);
                    v = min(v, old);
                }
                if (!v) break;
            }
        }
    }
}

// ---------------- finalize helpers ----------------
__device__ __forceinline__ float bsumf(float v, float* sh8, int tid) {
    #pragma unroll
    for (int o = 16; o; o >>= 1) v += __shfl_xor_sync(0xffffffffu, v, o);
    if ((tid & 31) == 0) sh8[tid >> 5] = v;
    __syncthreads();
    float r = sh8[0]+sh8[1]+sh8[2]+sh8[3]+sh8[4]+sh8[5]+sh8[6]+sh8[7];
    __syncthreads();
    return r;
}
__device__ __forceinline__ int bsumi(int v, int* sh8, int tid) {
    #pragma unroll
    for (int o = 16; o; o >>= 1) v += __shfl_xor_sync(0xffffffffu, v, o);
    if ((tid & 31) == 0) sh8[tid >> 5] = v;
    __syncthreads();
    int r = sh8[0]+sh8[1]+sh8[2]+sh8[3]+sh8[4]+sh8[5]+sh8[6]+sh8[7];
    __syncthreads();
    return r;
}
__device__ __forceinline__ void btop2(unsigned m1, unsigned m2,
                                      unsigned* s1, unsigned* s2, int tid,
                                      unsigned& o1, unsigned& o2) {
    #pragma unroll
    for (int o = 16; o; o >>= 1) {
        unsigned u1 = __shfl_xor_sync(0xffffffffu, m1, o);
        unsigned u2 = __shfl_xor_sync(0xffffffffu, m2, o);
        unsigned n1 = max(m1, u1);
        unsigned n2 = max(min(m1, u1), max(m2, u2));
        m1 = n1; m2 = n2;
    }
    if ((tid & 31) == 0) { s1[tid >> 5] = m1; s2[tid >> 5] = m2; }
    __syncthreads();
    unsigned t1 = 0, t2 = 0;
    #pragma unroll
    for (int w = 0; w < 8; w++) {
        unsigned a = s1[w], b = s2[w];
        unsigned n1 = max(t1, a);
        unsigned n2 = max(min(t1, a), max(t2, b));
        t1 = n1; t2 = n2;
    }
    __syncthreads();
    o1 = t1; o2 = t2;
}
__device__ __forceinline__ float quant2(float vmax, float vsec, int n) {
    if (n <= 0) return BIGV;
    float nf = (float)n;
    float q  = 1.0f - 1.0f / (nf + 1.0f);
    float pos = q * fmaxf(nf - 1.0f, 0.0f);
    int lo = (int)floorf(pos); lo = min(max(lo, 0), NB2 - 1);
    int hi = (int)ceilf(pos);  hi = min(max(hi, 0), NB2 - 1);
    float frac = pos - (float)lo;
    float vlo = (lo >= n - 1) ? vmax : vsec;
    float vhi = (hi >= n - 1) ? vmax : vsec;
    return vlo + (vhi - vlo) * frac;
}

// ---------------- finalize (+ combine): one block per batch ----------------
__global__ __launch_bounds__(256) void k_final(float* __restrict__ out) {
    __shared__ float ssel[NB2], sdd[NB2], sai[NB2], saj[NB2];
    __shared__ unsigned char svld[NB2], smF[NB2];
    __shared__ float shf[8];
    __shared__ int   shi[8];
    __shared__ unsigned sh1[8], sh2[8];
    __shared__ unsigned hist[256];
    __shared__ unsigned warpTot[8];
    __shared__ unsigned s_dig, s_bef;
    __shared__ int s_last;

    const int tid = threadIdx.x;
    const int b   = blockIdx.x;
    const float* ang = g_ang + b * QN;
    const float TWO_PI_F  = 6.283185307179586f;
    const float HALF_PI_F = 1.5707963267948966f;

    for (int s = tid; s < NB2; s += 256) {
        unsigned long long key = g_seg[(size_t)b * NB2 + s];
        float v = 0.f, ai = 0.f, aj = 0.f, d = 0.f;
        unsigned char vl = 0;
        if (key) {
            vl = 1;
            v = decf((unsigned)(key >> 32));
            unsigned ij = 0xFFFFFFFFu - (unsigned)key;
            int i = ij / QN, j = ij - i * QN;
            ai = ang[i]; aj = ang[j];
            float diff = fabsf(ai - aj);
            d = fminf(fminf(diff, TWO_PI_F - diff), HALF_PI_F);
        }
        ssel[s] = v; sai[s] = ai; saj[s] = aj; sdd[s] = d; svld[s] = vl;
    }
    __syncthreads();

    // S and top-2 of valid sel
    int c = 0; unsigned m1 = 0, m2 = 0;
    for (int s = tid; s < NB2; s += 256) {
        if (svld[s]) {
            c++;
            unsigned e = encf(ssel[s]);
            if (e > m1) { m2 = m1; m1 = e; } else if (e > m2) m2 = e;
        }
    }
    int S = bsumi(c, shi, tid);
    unsigned t1, t2; btop2(m1, m2, sh1, sh2, tid, t1, t2);
    float thr = quant2(decf(t1), decf(t2), S);

    // mask1
    c = 0;
    for (int s = tid; s < NB2; s += 256) {
        unsigned char m = (svld[s] && ssel[s] > thr) ? 1 : 0;
        smF[s] = m; c += m;
    }
    int c1 = bsumi(c, shi, tid);

    // fallback
    float th2 = decf(g_top4[b * 4 + 3]);
    bool use_fb = (c1 < 2);
    c = 0;
    for (int s = tid; s < NB2; s += 256) {
        unsigned char m = use_fb ? ((svld[s] && ssel[s] >= th2) ? 1 : 0) : smF[s];
        smF[s] = m; c += m;
    }
    int cnt = bsumi(c, shi, tid);

    // median of masked d via radix-select (warp-shfl scan: 1 barrier per pass)
    float med = BIGV;
    if (cnt > 0) {
        int kk = (cnt - 1) >> 1;
        unsigned prefix = 0;
        const int lane = tid & 31, w = tid >> 5;
        #pragma unroll
        for (int shift = 24; shift >= 0; shift -= 8) {
            hist[tid] = 0;
            __syncthreads();
            for (int s = tid; s < NB2; s += 256) {
                if (smF[s]) {
                    unsigned key = __float_as_uint(sdd[s]);
                    bool in = (shift == 24) || ((key >> (shift + 8)) == prefix);
                    if (in) atomicAdd(&hist[(key >> shift) & 255u], 1u);
                }
            }
            __syncthreads();
            unsigned my = hist[tid];
            unsigned v = my;
            #pragma unroll
            for (int o = 1; o < 32; o <<= 1) {
                unsigned u = __shfl_up_sync(0xffffffffu, v, o);
                if (lane >= o) v += u;
            }
            if (lane == 31) warpTot[w] = v;
            __syncthreads();
            unsigned off = 0;
            #pragma unroll
            for (int ww = 0; ww < 8; ww++) off += (ww < w) ? warpTot[ww] : 0u;
            unsigned cum = v + off, bef = cum - my;
            if ((int)cum > kk && (int)bef <= kk) { s_dig = (unsigned)tid; s_bef = bef; }
            __syncthreads();
            prefix = (prefix << 8) | s_dig;
            kk -= (int)s_bef;
            __syncthreads();
        }
        med = __uint_as_float(prefix);
    }
    float alpha = fminf(fmaxf(med, (float)(3.14159265358979323846 / 36.0)), HALF_PI_F);
    __syncthreads();

    // cooperative loss
    float fs = 0.f; int nc = 0;
    for (int s = tid; s < NB2; s += 256) {
        if (smF[s] && sdd[s] <= alpha) {
            float ai = sai[s], aj = saj[s];
            float mean = atan2f((sinf(ai) + sinf(aj)) * 0.5f,
                                (cosf(ai) + cosf(aj)) * 0.5f);
            float d1 = fabsf(ai - mean); d1 = fminf(fminf(d1, TWO_PI_F - d1), HALF_PI_F);
            float d2 = fabsf(aj - mean); d2 = fminf(fminf(d2, TWO_PI_F - d2), HALF_PI_F);
            fs += d1 * d1 + d2 * d2;
            nc++;
        }
    }
    float coop_sum = bsumf(fs, shf, tid);
    int n_coop = bsumi(nc, shi, tid);
    float coop_b = coop_sum / (float)max(n_coop, 1);

    // competitive loss
    c = 0; m1 = 0; m2 = 0;
    for (int s = tid; s < NB2; s += 256) {
        if (smF[s] && sdd[s] > alpha) {
            c++;
            unsigned e = encf(ssel[s]);
            if (e > m1) { m2 = m1; m1 = e; } else if (e > m2) m2 = e;
        }
    }
    int n_comp = bsumi(c, shi, tid);
    btop2(m1, m2, sh1, sh2, tid, t1, t2);
    float margin = quant2(decf(t1), decf(t2), n_comp);

    fs = 0.f;
    for (int s = tid; s < NB2; s += 256) {
        if (smF[s] && sdd[s] > alpha) {
            float viol = fmaxf(ssel[s] - margin, 0.f);
            fs += viol * viol;
        }
    }
    float comp_sum = bsumf(fs, shf, tid);
    float comp_b = comp_sum / (float)max(n_comp, 1);

    if (tid == 0) {
        g_res[b * 4 + 0] = coop_b;
        g_res[b * 4 + 1] = comp_b;
        g_res[b * 4 + 2] = (cnt > 0) ? 1.0f : 0.0f;
        __threadfence();
        unsigned old = atomicAdd(&g_done, 1u);
        s_last = (old == NBATCH - 1) ? 1 : 0;
    }
    __syncthreads();
    if (s_last && tid == 0) {
        __threadfence();
        float cs = 0.f, ps = 0.f; int nv = 0;
        for (int bb = 0; bb < NBATCH; bb++) {
            cs += g_res[bb * 4 + 0];
            ps += g_res[bb * 4 + 1];
            nv += (g_res[bb * 4 + 2] > 0.f) ? 1 : 0;
        }
        float denom = (float)max(nv, 1);
        out[0] = cs / denom;
        out[1] = ps / denom;
    }
}

// ---------------- launch ----------------
extern "C" void kernel_launch(void* const* d_in, const int* in_sizes, int n_in,
                              void* d_out, int out_size) {
    const float* qf = (const float*)d_in[0];   // [16,900,256]
    const float* pa = (const float*)d_in[1];   // [16,900,2]
    const float* W  = (const float*)d_in[2];   // [36,256]
    float* out = (float*)d_out;

    k_bins<<<81, 256>>>(pa);                   // 81*256 = NBATCH*NB2 exactly
    k_fuse<<<NBATCH * QN / 8, 256>>>(qf, W);
    dim3 g2(NTP2, NBATCH);
    k_pair<<<g2, 256>>>();
    k_final<<<NBATCH, 256>>>(out);
}

// round 6
// speedup vs baseline: 3.9095x; 1.0347x over previous
#include <cuda_runtime.h>
#include <math.h>
#include <stdint.h>

#define NBATCH 16
#define QN 900
#define QPAD 1024
#define HID 256
#define NBINS 36
#define NB2 1296
#define BIGV 1e9f

#define BM 128
#define KT 16            // K per chunk
#define KPAD 20          // padded floats per smem row (conflict-free frags)
#define TS (128 * KPAD)  // floats per tile buffer
#define NCH (HID / KT)   // 16
#define NTI2 8           // ceil(900/128)
#define NTP2 36          // 8*9/2
#define DYN_SMEM (2 * 4 * TS * 4)   // 81920 B

// ---------------- device globals ----------------
__device__ float g_hi[NBATCH * QPAD * HID];
__device__ float g_lo[NBATCH * QPAD * HID];
__device__ float g_ang[NBATCH * QN];
__device__ int   g_bin[NBATCH * QN];
__device__ unsigned long long g_seg[NBATCH * NB2];  // (ordfloat<<32)|(~pairidx)
__device__ unsigned int g_top4[NBATCH * 4];
__device__ float g_res[NBATCH * 4];
__device__ unsigned int g_done;

// ---------------- ordered-float encoding ----------------
__device__ __forceinline__ unsigned encf(float f) {
    unsigned u = __float_as_uint(f);
    return (u & 0x80000000u) ? ~u : (u | 0x80000000u);
}
__device__ __forceinline__ float decf(unsigned u) {
    unsigned v = (u & 0x80000000u) ? (u ^ 0x80000000u) : ~u;
    return __uint_as_float(v);
}
__device__ __forceinline__ float to_tf32(float x) {
    float r;
    asm("cvt.rna.tf32.f32 %0, %1;" : "=f"(r) : "f"(x));
    return r;
}
__device__ __forceinline__ uint32_t smem_u32(const void* p) {
    uint32_t a;
    asm("{ .reg .u64 t; cvta.to.shared.u64 t, %1; cvt.u32.u64 %0, t; }"
        : "=r"(a) : "l"(p));
    return a;
}
__device__ __forceinline__ void mma_tf32(float d[4], const uint32_t a[4],
                                         const uint32_t b[2]) {
    asm volatile(
        "mma.sync.aligned.m16n8k8.row.col.f32.tf32.tf32.f32 "
        "{%0,%1,%2,%3}, {%4,%5,%6,%7}, {%8,%9}, {%0,%1,%2,%3};"
        : "+f"(d[0]), "+f"(d[1]), "+f"(d[2]), "+f"(d[3])
        : "r"(a[0]), "r"(a[1]), "r"(a[2]), "r"(a[3]), "r"(b[0]), "r"(b[1]));
}
__device__ __forceinline__ void cp16(uint32_t dst, const float* src) {
    asm volatile("cp.async.cg.shared.global [%0], [%1], 16;"
                 :: "r"(dst), "l"(src));
}
#define CP_COMMIT() asm volatile("cp.async.commit_group;" ::: "memory")
#define CP_WAIT1()  asm volatile("cp.async.wait_group 1;" ::: "memory")
#define CP_WAIT0()  asm volatile("cp.async.wait_group 0;" ::: "memory")

// ---------------- bins: one thread per query (parallel fp64 atan2) + init ----------------
__global__ __launch_bounds__(256) void k_bins(const float* __restrict__ pa) {
    int gid = blockIdx.x * 256 + threadIdx.x;   // grid = 81*256 = NBATCH*NB2
    g_seg[gid] = 0ULL;
    if (gid < NBATCH * 4) g_top4[gid] = 0u;
    if (gid == 0)         g_done = 0u;

    if (gid < NBATCH * QN) {
        float x = pa[gid * 2 + 0], y = pa[gid * 2 + 1];
        float a = (float)atan2((double)y, (double)x);
        const float TWO_PI_F = 6.283185307179586f;
        if (a < 0.0f) a += TWO_PI_F;
        const float BIN_SIZE_F = (float)(6.283185307179586476925287 / 36.0);
        int bin = (int)(a / BIN_SIZE_F);
        bin = min(max(bin, 0), NBINS - 1);
        g_ang[gid] = a; g_bin[gid] = bin;
    }
}

// ---------------- fuse + normalize + tf32 hi/lo split: warp per row ----------------
__global__ __launch_bounds__(256) void k_fuse(const float* __restrict__ qf,
                                              const float* __restrict__ W) {
    const int warp = threadIdx.x >> 5;
    const int lane = threadIdx.x & 31;
    const int row = blockIdx.x * 8 + warp;   // 0..16383 (grid 2048)
    const int b = row >> 10, q = row & (QPAD - 1);

    float4* dh = (float4*)(g_hi + (size_t)row * HID);
    float4* dl = (float4*)(g_lo + (size_t)row * HID);
    const float4 z4 = make_float4(0.f, 0.f, 0.f, 0.f);

    if (q >= QN) {  // pad rows -> zero
        dh[lane] = z4; dh[lane + 32] = z4;
        dl[lane] = z4; dl[lane + 32] = z4;
        return;
    }
    const int bq = b * QN + q;
    const int bin = g_bin[bq];

    const float4* qr = (const float4*)(qf + (size_t)bq * HID);
    const float4* wr = (const float4*)(W + (size_t)bin * HID);
    float4 f0 = qr[lane], f1 = qr[lane + 32];
    float4 w0 = wr[lane], w1 = wr[lane + 32];
    f0.x += w0.x; f0.y += w0.y; f0.z += w0.z; f0.w += w0.w;
    f1.x += w1.x; f1.y += w1.y; f1.z += w1.z; f1.w += w1.w;
    float ss = f0.x*f0.x + f0.y*f0.y + f0.z*f0.z + f0.w*f0.w
             + f1.x*f1.x + f1.y*f1.y + f1.z*f1.z + f1.w*f1.w;
    #pragma unroll
    for (int o = 16; o; o >>= 1) ss += __shfl_xor_sync(0xffffffffu, ss, o);
    float nrm = fmaxf(sqrtf(ss), 1e-12f);

    float v[8] = {f0.x, f0.y, f0.z, f0.w, f1.x, f1.y, f1.z, f1.w};
    float h[8], l[8];
    #pragma unroll
    for (int i = 0; i < 8; i++) {
        float x = v[i] / nrm;
        float hi = to_tf32(x);
        float lo = to_tf32(x - hi);
        h[i] = hi; l[i] = lo;
    }
    dh[lane]      = make_float4(h[0], h[1], h[2], h[3]);
    dh[lane + 32] = make_float4(h[4], h[5], h[6], h[7]);
    dl[lane]      = make_float4(l[0], l[1], l[2], l[3]);
    dl[lane + 32] = make_float4(l[4], l[5], l[6], l[7]);
}

// ---------------- pair kernel: HMMA tf32 3-term GEMM + segment argmax ----------------
__global__ __launch_bounds__(256) void k_pair() {
    __shared__ unsigned long long sseg[NB2];
    __shared__ int sbi[BM], sbj[BM];
    __shared__ unsigned stop4[4];
    extern __shared__ float dynf[];
    const uint32_t dbu = smem_u32(dynf);

    const int b = blockIdx.y;
    int p = blockIdx.x;
    int ti = 0, rem = p;
    while (rem >= NTI2 - ti) { rem -= NTI2 - ti; ti++; }
    const int tj = ti + rem;
    const int i0 = ti * BM, j0 = tj * BM;

    const int tid = threadIdx.x, wid = tid >> 5, lane = tid & 31;
    const int moff = (wid >> 2) * 64, noff = (wid & 3) * 32;
    const int lr = lane >> 2, lc = lane & 3;

    for (int s = tid; s < NB2; s += 256) sseg[s] = 0ULL;
    if (tid < 4) stop4[tid] = 0u;
    if (tid < BM) {
        int gi = i0 + tid; sbi[tid] = (gi < QN) ? g_bin[b * QN + gi] : 0;
        int gj = j0 + tid; sbj[tid] = (gj < QN) ? g_bin[b * QN + gj] : 0;
    }

    const float* srcs[4];
    srcs[0] = g_hi + (size_t)(b * QPAD + i0) * HID;   // Ah
    srcs[1] = g_lo + (size_t)(b * QPAD + i0) * HID;   // Al
    srcs[2] = g_hi + (size_t)(b * QPAD + j0) * HID;   // Bh
    srcs[3] = g_lo + (size_t)(b * QPAD + j0) * HID;   // Bl

    // per-thread chunk-load coords: 512 float4 per tile, 2 per thread
    const int r0 = tid >> 2, c40 = tid & 3;             // elem 0: rows 0..63
    const int r1 = (tid + 256) >> 2, c41 = (tid + 256) & 3;  // elem 1: rows 64..127

    auto preload = [&](int ch, int stage) {
        #pragma unroll
        for (int t = 0; t < 4; t++) {
            const float* s = srcs[t] + ch * KT;
            uint32_t buf = dbu + (uint32_t)(((stage << 2) | t) * TS * 4);
            cp16(buf + (uint32_t)((r0 * KPAD + c40 * 4) * 4),
                 s + (size_t)r0 * HID + c40 * 4);
            cp16(buf + (uint32_t)((r1 * KPAD + c41 * 4) * 4),
                 s + (size_t)r1 * HID + c41 * 4);
        }
    };

    float acc[16][4];
    #pragma unroll
    for (int i = 0; i < 16; i++)
        #pragma unroll
        for (int e = 0; e < 4; e++) acc[i][e] = 0.0f;

    preload(0, 0);
    CP_COMMIT();

    #pragma unroll 1
    for (int ch = 0; ch < NCH; ch++) {
        const int cur = ch & 1;
        if (ch + 1 < NCH) {
            preload(ch + 1, cur ^ 1);
            CP_COMMIT();
            CP_WAIT1();
        } else {
            CP_WAIT0();
        }
        __syncthreads();

        const float* Ah = dynf + ((cur << 2) | 0) * TS;
        const float* Al = dynf + ((cur << 2) | 1) * TS;
        const float* Bh = dynf + ((cur << 2) | 2) * TS;
        const float* Bl = dynf + ((cur << 2) | 3) * TS;

        #pragma unroll
        for (int term = 0; term < 3; term++) {
            const float* Ap = (term == 2) ? Al : Ah;
            const float* Bp = (term == 1) ? Bl : Bh;
            #pragma unroll
            for (int ks = 0; ks < 2; ks++) {
                const int k0 = ks * 8;
                uint32_t af[4][4], bf[4][2];
                #pragma unroll
                for (int mt = 0; mt < 4; mt++) {
                    const float* base = Ap + (moff + mt * 16 + lr) * KPAD + k0 + lc;
                    af[mt][0] = __float_as_uint(base[0]);
                    af[mt][1] = __float_as_uint(base[8 * KPAD]);
                    af[mt][2] = __float_as_uint(base[4]);
                    af[mt][3] = __float_as_uint(base[8 * KPAD + 4]);
                }
                #pragma unroll
                for (int nt = 0; nt < 4; nt++) {
                    const float* base = Bp + (noff + nt * 8 + lr) * KPAD + k0 + lc;
                    bf[nt][0] = __float_as_uint(base[0]);
                    bf[nt][1] = __float_as_uint(base[4]);
                }
                #pragma unroll
                for (int mt = 0; mt < 4; mt++)
                    #pragma unroll
                    for (int nt = 0; nt < 4; nt++)
                        mma_tf32(acc[mt * 4 + nt], af[mt], bf[nt]);
            }
        }
        __syncthreads();
    }

    // epilogue: segment argmax (read-before-atomic) + local top4
    unsigned lt[4] = {0u, 0u, 0u, 0u};
    #pragma unroll
    for (int mt = 0; mt < 4; mt++) {
        #pragma unroll
        for (int nt = 0; nt < 4; nt++) {
            #pragma unroll
            for (int e = 0; e < 4; e++) {
                int lrow = moff + mt * 16 + lr + ((e & 2) ? 8 : 0);
                int lcol = noff + nt * 8 + 2 * lc + (e & 1);
                int gi = i0 + lrow, gj = j0 + lcol;
                if (gi < QN && gj < QN && gi < gj) {
                    float v = acc[mt * 4 + nt][e];
                    unsigned ev = encf(v);
                    if (ev > lt[3]) {
                        if (ev > lt[0])      { lt[3]=lt[2]; lt[2]=lt[1]; lt[1]=lt[0]; lt[0]=ev; }
                        else if (ev > lt[1]) { lt[3]=lt[2]; lt[2]=lt[1]; lt[1]=ev; }
                        else if (ev > lt[2]) { lt[3]=lt[2]; lt[2]=ev; }
                        else                 { lt[3]=ev; }
                    }
                    int bi = sbi[lrow], bj = sbj[lcol];
                    int sgm = min(bi, bj) * NBINS + max(bi, bj);
                    unsigned long long key =
                        ((unsigned long long)ev << 32) |
                        (unsigned long long)(0xFFFFFFFFu - (unsigned)(gi * QN + gj));
                    if (key > sseg[sgm]) atomicMax(&sseg[sgm], key);
                }
            }
        }
    }
    #pragma unroll
    for (int q4 = 0; q4 < 4; q4++) {
        unsigned v = lt[q4];
        if (!v) break;
        #pragma unroll
        for (int sl = 0; sl < 4; sl++) {
            if (v > stop4[sl]) {
                unsigned old = atomicMax(&stop4[sl], v);
                v = min(v, old);
            }
            if (!v) break;
        }
    }
    __syncthreads();

    unsigned long long* gs = g_seg + (size_t)b * NB2;
    for (int s = tid; s < NB2; s += 256) {
        unsigned long long k = sseg[s];
        if (k && k > gs[s]) atomicMax(&gs[s], k);
    }
    if (tid == 0) {
        unsigned* gt = g_top4 + b * 4;
        #pragma unroll
        for (int q4 = 0; q4 < 4; q4++) {
            unsigned v = stop4[q4];
            if (!v) continue;
            for (int sl = 0; sl < 4; sl++) {
                if (v > gt[sl]) {
                    unsigned old = atomicMax(&gt[sl], v);
                    v = min(v, old);
                }
                if (!v) break;
            }
        }
    }
}

// ---------------- finalize helpers ----------------
__device__ __forceinline__ float bsumf(float v, float* sh8, int tid) {
    #pragma unroll
    for (int o = 16; o; o >>= 1) v += __shfl_xor_sync(0xffffffffu, v, o);
    if ((tid & 31) == 0) sh8[tid >> 5] = v;
    __syncthreads();
    float r = sh8[0]+sh8[1]+sh8[2]+sh8[3]+sh8[4]+sh8[5]+sh8[6]+sh8[7];
    __syncthreads();
    return r;
}
__device__ __forceinline__ int bsumi(int v, int* sh8, int tid) {
    #pragma unroll
    for (int o = 16; o; o >>= 1) v += __shfl_xor_sync(0xffffffffu, v, o);
    if ((tid & 31) == 0) sh8[tid >> 5] = v;
    __syncthreads();
    int r = sh8[0]+sh8[1]+sh8[2]+sh8[3]+sh8[4]+sh8[5]+sh8[6]+sh8[7];
    __syncthreads();
    return r;
}
__device__ __forceinline__ void btop2(unsigned m1, unsigned m2,
                                      unsigned* s1, unsigned* s2, int tid,
                                      unsigned& o1, unsigned& o2) {
    #pragma unroll
    for (int o = 16; o; o >>= 1) {
        unsigned u1 = __shfl_xor_sync(0xffffffffu, m1, o);
        unsigned u2 = __shfl_xor_sync(0xffffffffu, m2, o);
        unsigned n1 = max(m1, u1);
        unsigned n2 = max(min(m1, u1), max(m2, u2));
        m1 = n1; m2 = n2;
    }
    if ((tid & 31) == 0) { s1[tid >> 5] = m1; s2[tid >> 5] = m2; }
    __syncthreads();
    unsigned t1 = 0, t2 = 0;
    #pragma unroll
    for (int w = 0; w < 8; w++) {
        unsigned a = s1[w], bb = s2[w];
        unsigned n1 = max(t1, a);
        unsigned n2 = max(min(t1, a), max(t2, bb));
        t1 = n1; t2 = n2;
    }
    __syncthreads();
    o1 = t1; o2 = t2;
}
__device__ __forceinline__ float quant2(float vmax, float vsec, int n) {
    if (n <= 0) return BIGV;
    float nf = (float)n;
    float q  = 1.0f - 1.0f / (nf + 1.0f);
    float pos = q * fmaxf(nf - 1.0f, 0.0f);
    int lo = (int)floorf(pos); lo = min(max(lo, 0), NB2 - 1);
    int hi = (int)ceilf(pos);  hi = min(max(hi, 0), NB2 - 1);
    float frac = pos - (float)lo;
    float vlo = (lo >= n - 1) ? vmax : vsec;
    float vhi = (hi >= n - 1) ? vmax : vsec;
    return vlo + (vhi - vlo) * frac;
}

// ---------------- finalize (+ combine): one block per batch ----------------
__global__ __launch_bounds__(256) void k_final(float* __restrict__ out) {
    __shared__ float ssel[NB2], sdd[NB2], sai[NB2], saj[NB2];
    __shared__ unsigned char svld[NB2], smF[NB2];
    __shared__ float shf[8];
    __shared__ int   shi[8];
    __shared__ unsigned sh1[8], sh2[8];
    __shared__ unsigned hist[256];
    __shared__ unsigned warpTot[8];
    __shared__ unsigned s_dig, s_bef;
    __shared__ int s_last;

    const int tid = threadIdx.x;
    const int b   = blockIdx.x;
    const float* ang = g_ang + b * QN;
    const float TWO_PI_F  = 6.283185307179586f;
    const float HALF_PI_F = 1.5707963267948966f;

    for (int s = tid; s < NB2; s += 256) {
        unsigned long long key = g_seg[(size_t)b * NB2 + s];
        float v = 0.f, ai = 0.f, aj = 0.f, d = 0.f;
        unsigned char vl = 0;
        if (key) {
            vl = 1;
            v = decf((unsigned)(key >> 32));
            unsigned ij = 0xFFFFFFFFu - (unsigned)key;
            int i = ij / QN, j = ij - i * QN;
            ai = ang[i]; aj = ang[j];
            float diff = fabsf(ai - aj);
            d = fminf(fminf(diff, TWO_PI_F - diff), HALF_PI_F);
        }
        ssel[s] = v; sai[s] = ai; saj[s] = aj; sdd[s] = d; svld[s] = vl;
    }
    __syncthreads();

    int c = 0; unsigned m1 = 0, m2 = 0;
    for (int s = tid; s < NB2; s += 256) {
        if (svld[s]) {
            c++;
            unsigned e = encf(ssel[s]);
            if (e > m1) { m2 = m1; m1 = e; } else if (e > m2) m2 = e;
        }
    }
    int S = bsumi(c, shi, tid);
    unsigned t1, t2; btop2(m1, m2, sh1, sh2, tid, t1, t2);
    float thr = quant2(decf(t1), decf(t2), S);

    c = 0;
    for (int s = tid; s < NB2; s += 256) {
        unsigned char m = (svld[s] && ssel[s] > thr) ? 1 : 0;
        smF[s] = m; c += m;
    }
    int c1 = bsumi(c, shi, tid);

    float th2 = decf(g_top4[b * 4 + 3]);
    bool use_fb = (c1 < 2);
    c = 0;
    for (int s = tid; s < NB2; s += 256) {
        unsigned char m = use_fb ? ((svld[s] && ssel[s] >= th2) ? 1 : 0) : smF[s];
        smF[s] = m; c += m;
    }
    int cnt = bsumi(c, shi, tid);

    float med = BIGV;
    if (cnt > 0) {
        int kk = (cnt - 1) >> 1;
        unsigned prefix = 0;
        const int lane = tid & 31, w = tid >> 5;
        #pragma unroll
        for (int shift = 24; shift >= 0; shift -= 8) {
            hist[tid] = 0;
            __syncthreads();
            for (int s = tid; s < NB2; s += 256) {
                if (smF[s]) {
                    unsigned key = __float_as_uint(sdd[s]);
                    bool in = (shift == 24) || ((key >> (shift + 8)) == prefix);
                    if (in) atomicAdd(&hist[(key >> shift) & 255u], 1u);
                }
            }
            __syncthreads();
            unsigned my = hist[tid];
            unsigned v = my;
            #pragma unroll
            for (int o = 1; o < 32; o <<= 1) {
                unsigned u = __shfl_up_sync(0xffffffffu, v, o);
                if (lane >= o) v += u;
            }
            if (lane == 31) warpTot[w] = v;
            __syncthreads();
            unsigned off = 0;
            #pragma unroll
            for (int ww = 0; ww < 8; ww++) off += (ww < w) ? warpTot[ww] : 0u;
            unsigned cum = v + off, bef = cum - my;
            if ((int)cum > kk && (int)bef <= kk) { s_dig = (unsigned)tid; s_bef = bef; }
            __syncthreads();
            prefix = (prefix << 8) | s_dig;
            kk -= (int)s_bef;
            __syncthreads();
        }
        med = __uint_as_float(prefix);
    }
    float alpha = fminf(fmaxf(med, (float)(3.14159265358979323846 / 36.0)), HALF_PI_F);
    __syncthreads();

    float fs = 0.f; int nc = 0;
    for (int s = tid; s < NB2; s += 256) {
        if (smF[s] && sdd[s] <= alpha) {
            float ai = sai[s], aj = saj[s];
            float mean = atan2f((sinf(ai) + sinf(aj)) * 0.5f,
                                (cosf(ai) + cosf(aj)) * 0.5f);
            float d1 = fabsf(ai - mean); d1 = fminf(fminf(d1, TWO_PI_F - d1), HALF_PI_F);
            float d2 = fabsf(aj - mean); d2 = fminf(fminf(d2, TWO_PI_F - d2), HALF_PI_F);
            fs += d1 * d1 + d2 * d2;
            nc++;
        }
    }
    float coop_sum = bsumf(fs, shf, tid);
    int n_coop = bsumi(nc, shi, tid);
    float coop_b = coop_sum / (float)max(n_coop, 1);

    c = 0; m1 = 0; m2 = 0;
    for (int s = tid; s < NB2; s += 256) {
        if (smF[s] && sdd[s] > alpha) {
            c++;
            unsigned e = encf(ssel[s]);
            if (e > m1) { m2 = m1; m1 = e; } else if (e > m2) m2 = e;
        }
    }
    int n_comp = bsumi(c, shi, tid);
    btop2(m1, m2, sh1, sh2, tid, t1, t2);
    float margin = quant2(decf(t1), decf(t2), n_comp);

    fs = 0.f;
    for (int s = tid; s < NB2; s += 256) {
        if (smF[s] && sdd[s] > alpha) {
            float viol = fmaxf(ssel[s] - margin, 0.f);
            fs += viol * viol;
        }
    }
    float comp_sum = bsumf(fs, shf, tid);
    float comp_b = comp_sum / (float)max(n_comp, 1);

    if (tid == 0) {
        g_res[b * 4 + 0] = coop_b;
        g_res[b * 4 + 1] = comp_b;
        g_res[b * 4 + 2] = (cnt > 0) ? 1.0f : 0.0f;
        __threadfence();
        unsigned old = atomicAdd(&g_done, 1u);
        s_last = (old == NBATCH - 1) ? 1 : 0;
    }
    __syncthreads();
    if (s_last && tid == 0) {
        __threadfence();
        float cs = 0.f, ps = 0.f; int nv = 0;
        for (int bb = 0; bb < NBATCH; bb++) {
            cs += g_res[bb * 4 + 0];
            ps += g_res[bb * 4 + 1];
            nv += (g_res[bb * 4 + 2] > 0.f) ? 1 : 0;
        }
        float denom = (float)max(nv, 1);
        out[0] = cs / denom;
        out[1] = ps / denom;
    }
}

// ---------------- launch ----------------
extern "C" void kernel_launch(void* const* d_in, const int* in_sizes, int n_in,
                              void* d_out, int out_size) {
    const float* qf = (const float*)d_in[0];   // [16,900,256]
    const float* pa = (const float*)d_in[1];   // [16,900,2]
    const float* W  = (const float*)d_in[2];   // [36,256]
    float* out = (float*)d_out;

    cudaFuncSetAttribute(k_pair, cudaFuncAttributeMaxDynamicSharedMemorySize, DYN_SMEM);

    k_bins<<<81, 256>>>(pa);                        // 81*256 = NBATCH*NB2 exactly
    k_fuse<<<NBATCH * QPAD / 8, 256>>>(qf, W);      // 2048 blocks
    dim3 g2(NTP2, NBATCH);
    k_pair<<<g2, 256, DYN_SMEM>>>();
    k_final<<<NBATCH, 256>>>(out);
}